// round 12
// baseline (speedup 1.0000x reference)
#include <cuda_runtime.h>
#include <cuda_bf16.h>
#include <math.h>
#include <stdint.h>

#define Bsz 256
#define Vn  50
#define Nn  64
#define Dd  128
#define NDd 8192
#define Hh  384
#define Ll  8
#define CHc 48
#define KW  10
#define OUTd 128
#define Gg  1552
#define GgPad 1664
#define Mtot 12800          /* B*V ; m = v*Bsz + b (v-major) */
#define NIT 256             /* 8192 / 32 */
#define NSTG 4              /* pipeline stages, 32KB each */

typedef unsigned long long ull;

// ---------------- device scratch (no allocs allowed) ----------------
__device__ float g_xk[(size_t)Mtot * Gg];          // [v*Bsz+b][g]
__device__ float g_xout[Bsz * Gg];
__device__ float g_h[Bsz * Hh];
__device__ float g_c[Bsz * Hh];
__device__ float g_tmp_h[KW * Bsz * Hh];
__device__ float g_tmp_dis[KW * Bsz];
__device__ float g_ld[Bsz * KW];
__device__ float g_theme[Bsz * Hh];
__device__ float g_conv_part[KW * Bsz * Hh];
__device__ float g_rnn_last[Bsz * Hh];
__device__ float g_Wct[KW * Hh * Hh];
__device__ float g_Wot[Hh * OUTd];
__device__ int   g_last[Bsz];
__device__ int   g_needed[64];
// pre-tiled, pre-swizzled 8KB tiles: [tileIdx*256 + ck] * 4096 bf16 elems
// phys within tile: row*64 + ((ch ^ ((row>>1)&3))<<4) + byte_in_16B
__device__ __align__(256) __nv_bfloat16 g_Wk_hi[(size_t)GgPad * NDd];
__device__ __align__(256) __nv_bfloat16 g_Wk_lo[(size_t)GgPad * NDd];
__device__ __align__(256) __nv_bfloat16 g_A_hi[(size_t)Mtot * NDd];
__device__ __align__(256) __nv_bfloat16 g_A_lo[(size_t)Mtot * NDd];

__device__ __forceinline__ float sigf(float x) { return 1.0f / (1.0f + expf(-x)); }

__device__ __forceinline__ uint32_t smem_u32(const void* p) {
    uint32_t a;
    asm("{ .reg .u64 t; cvta.to.shared.u64 t, %1; cvt.u32.u64 %0, t; }" : "=r"(a) : "l"(p));
    return a;
}

// ---------------- sm_90-era async + sm_80 tensor path (valid under .target sm_103) ----------------
__device__ __forceinline__ void ldm4(uint32_t* r, uint32_t addr) {
    asm volatile("ldmatrix.sync.aligned.m8n8.x4.shared.b16 {%0,%1,%2,%3}, [%4];"
                 : "=r"(r[0]), "=r"(r[1]), "=r"(r[2]), "=r"(r[3]) : "r"(addr));
}
__device__ __forceinline__ void mma16816(float* c, const uint32_t* a, const uint32_t* b) {
    asm volatile("mma.sync.aligned.m16n8k16.row.col.f32.bf16.bf16.f32 "
                 "{%0,%1,%2,%3}, {%4,%5,%6,%7}, {%8,%9}, {%0,%1,%2,%3};"
                 : "+f"(c[0]), "+f"(c[1]), "+f"(c[2]), "+f"(c[3])
                 : "r"(a[0]), "r"(a[1]), "r"(a[2]), "r"(a[3]), "r"(b[0]), "r"(b[1]));
}

#define MB_INIT(a, c) \
    asm volatile("mbarrier.init.shared.b64 [%0], %1;" :: "r"((uint32_t)(a)), "r"((uint32_t)(c)) : "memory")
#define MB_EXPECT(a, tx) \
    asm volatile("mbarrier.arrive.expect_tx.shared.b64 _, [%0], %1;" :: "r"((uint32_t)(a)), "r"((uint32_t)(tx)) : "memory")
#define MB_WAIT(a, par) do {                                                       \
    uint32_t _m = (uint32_t)(a), _p = (uint32_t)(par), _d;                         \
    asm volatile("{\n\t.reg .pred p;\n\t"                                          \
        "mbarrier.try_wait.parity.shared.b64 p, [%1], %2;\n\t"                     \
        "selp.b32 %0, 1, 0, p;\n\t}" : "=r"(_d) : "r"(_m), "r"(_p) : "memory");    \
    if (!_d) {                                                                     \
        asm volatile("{\n\t.reg .pred P1;\n\t"                                     \
        "WL_%=:\n\t"                                                               \
        "mbarrier.try_wait.parity.shared.b64 P1, [%0], %1;\n\t"                    \
        "@P1 bra.uni WD_%=;\n\t"                                                   \
        "bra.uni WL_%=;\n\t"                                                       \
        "WD_%=:\n\t}" :: "r"(_m), "r"(_p) : "memory");                             \
    } } while (0)
#define FENCE_ASYNC() asm volatile("fence.proxy.async.shared::cta;" ::: "memory")
#define BULK_G2S(dst, src, sz, mbar) \
    asm volatile("cp.async.bulk.shared::cta.global.mbarrier::complete_tx::bytes [%0], [%1], %2, [%3];" \
        :: "r"((uint32_t)(dst)), "l"(__cvta_generic_to_global(src)), "r"((uint32_t)(sz)), "r"((uint32_t)(mbar)) : "memory")

// ---------------- small init kernels ----------------
__global__ void k_zero() {
    int i = blockIdx.x * blockDim.x + threadIdx.x;
    int st = gridDim.x * blockDim.x;
    for (int k = i; k < KW * Bsz * Hh; k += st) g_tmp_h[k] = 0.f;
    for (int k = i; k < Bsz * Hh; k += st) { g_c[k] = 0.f; g_h[k] = 0.f; }
    for (int k = i; k < KW * Bsz; k += st) g_tmp_dis[k] = 0.f;
    if (i < 64) g_needed[i] = 0;
}

__global__ void k_last(const unsigned char* __restrict__ mask) {
    int b = blockIdx.x, v = threadIdx.x;   // blockDim = 64
    __shared__ int nv[64];
    int val = 0;
    if (v < Vn) {
        const unsigned char* mp = mask + ((size_t)b * Vn + v) * Nn;
        int allp = 1;
        for (int n = 0; n < Nn; n++) allp &= (mp[n] != 0);
        val = allp ? 0 : 1;
    }
    nv[v] = val;
    __syncthreads();
    if (v == 0) {
        int c = 0;
        for (int i = 0; i < Vn; i++) c += nv[i];
        int last = c - 1;
        if (last < 0) last += Vn;
        g_last[b] = last;
        g_needed[last] = 1;
    }
}

__global__ void k_wtrans(const float* __restrict__ Wc, const float* __restrict__ Wo) {
    int i = blockIdx.x * blockDim.x + threadIdx.x;
    int st = gridDim.x * blockDim.x;
    for (int idx = i; idx < Hh * Hh * KW; idx += st) {
        int o = idx / (Hh * KW);
        int rem = idx - o * (Hh * KW);
        int h = rem / KW;
        int j = rem - h * KW;
        g_Wct[((size_t)j * Hh + h) * Hh + o] = Wc[idx];
    }
    for (int idx = i; idx < OUTd * Hh; idx += st) {
        int o = idx / Hh, k = idx - o * Hh;
        g_Wot[k * OUTd + o] = Wo[idx];
    }
}

// decode physical element-group position -> (tileRow, logical k-chunk elem)
// e4 = group of 4 bf16 (8 bytes). byte off in tile = (e4*8)&8191.
__device__ __forceinline__ void dec_tile(size_t e4, int& tile, int& row, int& kk) {
    tile = (int)(e4 >> 10);                    // 1024 groups per 8KB tile
    int off = ((int)e4 & 1023) * 8;            // byte offset in tile
    row = off >> 6;
    int w = off & 63;
    int chp = w >> 4;
    int ch = chp ^ ((row >> 1) & 3);
    kk = ch * 8 + ((w & 15) >> 1);             // 0..28, step 4
}

// split Wk[:, :8192] into bf16 hi/lo tiles [ni*256+ck] (GgPad rows, zero pad)
__global__ void k_wkbf(const float* __restrict__ Wk) {
    size_t i = (size_t)blockIdx.x * blockDim.x + threadIdx.x;
    size_t st = (size_t)gridDim.x * blockDim.x;
    const size_t TOT4 = (size_t)GgPad * NDd / 4;
    uint2* ph = (uint2*)g_Wk_hi;
    uint2* pl = (uint2*)g_Wk_lo;
    for (size_t e4 = i; e4 < TOT4; e4 += st) {
        int tile, row, kk;
        dec_tile(e4, tile, row, kk);
        int ni = tile >> 8, ck = tile & 255;
        int g = ni * 128 + row;
        int k = ck * 32 + kk;
        float v0 = 0.f, v1 = 0.f, v2 = 0.f, v3 = 0.f;
        if (g < Gg) {
            const float* wr = Wk + (size_t)g * (NDd + 1) + k;
            v0 = wr[0]; v1 = wr[1]; v2 = wr[2]; v3 = wr[3];
        }
        __nv_bfloat16 h0 = __float2bfloat16_rn(v0), h1 = __float2bfloat16_rn(v1),
                      h2 = __float2bfloat16_rn(v2), h3 = __float2bfloat16_rn(v3);
        __nv_bfloat16 l0 = __float2bfloat16_rn(v0 - __bfloat162float(h0));
        __nv_bfloat16 l1 = __float2bfloat16_rn(v1 - __bfloat162float(h1));
        __nv_bfloat16 l2 = __float2bfloat16_rn(v2 - __bfloat162float(h2));
        __nv_bfloat16 l3 = __float2bfloat16_rn(v3 - __bfloat162float(h3));
        __nv_bfloat162 hA; hA.x = h0; hA.y = h1;
        __nv_bfloat162 hB; hB.x = h2; hB.y = h3;
        __nv_bfloat162 lA; lA.x = l0; lA.y = l1;
        __nv_bfloat162 lB; lB.x = l2; lB.y = l3;
        ph[e4] = make_uint2(*(uint32_t*)&hA, *(uint32_t*)&hB);
        pl[e4] = make_uint2(*(uint32_t*)&lA, *(uint32_t*)&lB);
    }
}

// gather x = embed[node_ids], split to bf16 hi/lo tiles [mi*256+ck]; m = v*Bsz+b
// processes tile range [tile0, tile0+ntiles) so chunks can pipeline with the GEMM
__global__ void k_split_rng(const int* __restrict__ ids, const float4* __restrict__ ef4,
                            int tile0, int ntiles) {
    size_t i = (size_t)blockIdx.x * blockDim.x + threadIdx.x;
    size_t st = (size_t)gridDim.x * blockDim.x;
    const size_t base = (size_t)tile0 << 10;
    const size_t CNT4 = (size_t)ntiles << 10;
    uint2* ph = (uint2*)g_A_hi;
    uint2* pl = (uint2*)g_A_lo;
    for (size_t r = i; r < CNT4; r += st) {
        size_t e4 = base + r;
        int tile, row, kk;
        dec_tile(e4, tile, row, kk);
        int mi = tile >> 8, ck = tile & 255;
        int m = mi * 128 + row;
        int k = ck * 32 + kk;
        int v_ = m >> 8, b = m & 255;
        int id = __ldg(&ids[(b * Vn + v_) * Nn + (k >> 7)]);
        float4 v = __ldg(&ef4[(size_t)id * 32 + ((k & 127) >> 2)]);
        __nv_bfloat16 h0 = __float2bfloat16_rn(v.x), h1 = __float2bfloat16_rn(v.y),
                      h2 = __float2bfloat16_rn(v.z), h3 = __float2bfloat16_rn(v.w);
        __nv_bfloat16 l0 = __float2bfloat16_rn(v.x - __bfloat162float(h0));
        __nv_bfloat16 l1 = __float2bfloat16_rn(v.y - __bfloat162float(h1));
        __nv_bfloat16 l2 = __float2bfloat16_rn(v.z - __bfloat162float(h2));
        __nv_bfloat16 l3 = __float2bfloat16_rn(v.w - __bfloat162float(h3));
        __nv_bfloat162 hA; hA.x = h0; hA.y = h1;
        __nv_bfloat162 hB; hB.x = h2; hB.y = h3;
        __nv_bfloat162 lA; lA.x = l0; lA.y = l1;
        __nv_bfloat162 lB; lB.x = l2; lB.y = l3;
        ph[e4] = make_uint2(*(uint32_t*)&hA, *(uint32_t*)&hB);
        pl[e4] = make_uint2(*(uint32_t*)&lA, *(uint32_t*)&lB);
    }
}

// ---------------- tensor-core input projection: bulk-TMA loader + mma.sync ----------------
// XK[m,g] = sum_d x[m,d]*Wk[g,d] + (bk+br)[g] + vt[m]*(Wk[g,ND]+Wr[g,H])
// bf16 split: xh*wh + xh*wl + xl*wh, fp32 accumulators.
// smem per stage 32KB: Ah[8K] Al[8K] Bh[8K] Bl[8K]; NSTG=4 stages = 128KB dynamic.
// loader: 4x cp.async.bulk (8KB each) per iter issued by thread 0, mbarrier completion.

__global__ __launch_bounds__(256, 1)
void k_xk_mma(const float* __restrict__ vt, const float* __restrict__ Wk,
              const float* __restrict__ bk, const float* __restrict__ Wr,
              const float* __restrict__ br, int mi0)
{
    extern __shared__ char dsm[];
    __shared__ float bias_s[128], wl_s[128], vt_s[128];
    __shared__ __align__(8) ull mbars[NSTG];
    const uint32_t smb = smem_u32(dsm);
    const int tid = threadIdx.x;
    const int wid = tid >> 5, lane = tid & 31;
    const int wm = wid & 1, wn = wid >> 1;    // warp tile: 64 rows x 32 cols

    const int mi = mi0 + blockIdx.y;          // m-tile (128 v-major rows)
    const int ni = blockIdx.x;
    const int m0 = mi * 128, n0 = ni * 128;

    if (tid < NSTG) MB_INIT(smem_u32(&mbars[tid]), 1);
    if (tid < 128) {
        int g = n0 + tid;
        if (g < Gg) {
            bias_s[tid] = bk[g] + br[g];
            wl_s[tid] = Wk[(size_t)g * (NDd + 1) + NDd] + Wr[(size_t)g * (Hh + 1) + Hh];
        } else { bias_s[tid] = 0.f; wl_s[tid] = 0.f; }
        int m = m0 + tid;
        int v_ = m >> 8, b = m & 255;
        vt_s[tid] = __ldg(&vt[b * Vn + v_]);
    }
    FENCE_ASYNC();
    __syncthreads();

    float acc[4][4][4];
#pragma unroll
    for (int a = 0; a < 4; a++)
#pragma unroll
        for (int b = 0; b < 4; b++)
#pragma unroll
            for (int c = 0; c < 4; c++) acc[a][b][c] = 0.f;

    // prologue: fill NSTG-1 stages
    if (tid == 0) {
#pragma unroll
        for (int s = 0; s < NSTG - 1; s++) {
            uint32_t mb = smem_u32(&mbars[s]);
            uint32_t so = smb + s * 32768;
            size_t at = ((size_t)mi * 256 + s) * 4096;
            size_t bt = ((size_t)ni * 256 + s) * 4096;
            MB_EXPECT(mb, 32768u);
            BULK_G2S(so,         g_A_hi + at, 8192u, mb);
            BULK_G2S(so + 8192,  g_A_lo + at, 8192u, mb);
            BULK_G2S(so + 16384, g_Wk_hi + bt, 8192u, mb);
            BULK_G2S(so + 24576, g_Wk_lo + bt, 8192u, mb);
        }
    }

    for (int ck = 0; ck < NIT; ck++) {
        const int st = ck & (NSTG - 1);
        MB_WAIT(smem_u32(&mbars[st]), (ck >> 2) & 1);

        uint32_t so = smb + st * 32768;
#pragma unroll
        for (int kc = 0; kc < 2; kc++) {
            uint32_t a_hi[4][4], a_lo[4][4], b_hi[4][2], b_lo[4][2];
            const int arow = wm * 64 + (lane & 15);
            const int ach = 2 * kc + (lane >> 4);
#pragma unroll
            for (int mt = 0; mt < 4; mt++) {
                int r = arow + mt * 16;
                uint32_t ph = (uint32_t)(r * 64 + ((ach ^ ((r >> 1) & 3)) << 4));
                ldm4(a_hi[mt], so + ph);
                ldm4(a_lo[mt], so + 8192 + ph);
            }
            const int brow = wn * 32 + ((lane >> 4) & 1) * 8 + (lane & 7);
            const int bch = 2 * kc + ((lane >> 3) & 1);
#pragma unroll
            for (int np = 0; np < 2; np++) {
                int r = brow + np * 16;
                uint32_t ph = (uint32_t)(r * 64 + ((bch ^ ((r >> 1) & 3)) << 4));
                uint32_t t[4];
                ldm4(t, so + 16384 + ph);
                b_hi[np * 2][0] = t[0]; b_hi[np * 2][1] = t[1];
                b_hi[np * 2 + 1][0] = t[2]; b_hi[np * 2 + 1][1] = t[3];
                ldm4(t, so + 24576 + ph);
                b_lo[np * 2][0] = t[0]; b_lo[np * 2][1] = t[1];
                b_lo[np * 2 + 1][0] = t[2]; b_lo[np * 2 + 1][1] = t[3];
            }
#pragma unroll
            for (int mt = 0; mt < 4; mt++)
#pragma unroll
                for (int nt = 0; nt < 4; nt++) mma16816(acc[mt][nt], a_hi[mt], b_hi[nt]);
#pragma unroll
            for (int mt = 0; mt < 4; mt++)
#pragma unroll
                for (int nt = 0; nt < 4; nt++) mma16816(acc[mt][nt], a_hi[mt], b_lo[nt]);
#pragma unroll
            for (int mt = 0; mt < 4; mt++)
#pragma unroll
                for (int nt = 0; nt < 4; nt++) mma16816(acc[mt][nt], a_lo[mt], b_hi[nt]);
        }
        __syncthreads();   // all threads done reading stage st
        if (tid == 0 && ck + NSTG - 1 < NIT) {
            int nk = ck + NSTG - 1;
            int ns = nk & (NSTG - 1);          // == (ck-1)&3, freed by barrier above
            uint32_t mb = smem_u32(&mbars[ns]);
            uint32_t nso = smb + ns * 32768;
            size_t at = ((size_t)mi * 256 + nk) * 4096;
            size_t bt = ((size_t)ni * 256 + nk) * 4096;
            MB_EXPECT(mb, 32768u);
            BULK_G2S(nso,         g_A_hi + at, 8192u, mb);
            BULK_G2S(nso + 8192,  g_A_lo + at, 8192u, mb);
            BULK_G2S(nso + 16384, g_Wk_hi + bt, 8192u, mb);
            BULK_G2S(nso + 24576, g_Wk_lo + bt, 8192u, mb);
        }
    }

    // epilogue: direct register -> gmem, fold bias + interval term
#pragma unroll
    for (int mt = 0; mt < 4; mt++) {
        int rl0 = wm * 64 + mt * 16 + (lane >> 2);
        int rl1 = rl0 + 8;
        float v0 = vt_s[rl0], v1 = vt_s[rl1];
        size_t ro0 = (size_t)(m0 + rl0) * Gg;
        size_t ro1 = (size_t)(m0 + rl1) * Gg;
#pragma unroll
        for (int nt = 0; nt < 4; nt++) {
            int gl = wn * 32 + nt * 8 + (lane & 3) * 2;
            int g = n0 + gl;
            if (g < Gg) {
                g_xk[ro0 + g] = acc[mt][nt][0] + bias_s[gl] + v0 * wl_s[gl];
                g_xk[ro1 + g] = acc[mt][nt][2] + bias_s[gl] + v1 * wl_s[gl];
            }
            if (g + 1 < Gg) {
                g_xk[ro0 + g + 1] = acc[mt][nt][1] + bias_s[gl + 1] + v0 * wl_s[gl + 1];
                g_xk[ro1 + g + 1] = acc[mt][nt][3] + bias_s[gl + 1] + v1 * wl_s[gl + 1];
            }
        }
    }
}

// ---------------- recurrent GEMM: xout = XK[t*Bsz+b] + h @ Wr[:, :H].T ----------------
#define RBM 64
#define RBN 64
#define RBK 32

#define RC_LOAD(kc_) {                                                          \
    int kb_ = (kc_) * RBK;                                                      \
    a_s0 = *(const float4*)(&g_h[(b0 + rA0) * Hh + kb_ + (cA0 << 2)]);          \
    a_s1 = *(const float4*)(&g_h[(b0 + rA1) * Hh + kb_ + (cA0 << 2)]);          \
    _Pragma("unroll")                                                           \
    for (int i_ = 0; i_ < 8; i_++) {                                            \
        int e_ = (i_ << 8) + tid; int kl_ = e_ & 31, gl_ = e_ >> 5;             \
        int g_ = g0 + gl_;                                                      \
        b_s[i_] = (g_ < Gg) ? Wr[(size_t)g_ * (Hh + 1) + kb_ + kl_] : 0.f;      \
    } }

#define RC_STORE() {                                                            \
    As[(cA0 << 2) + 0][rA0] = a_s0.x; As[(cA0 << 2) + 1][rA0] = a_s0.y;         \
    As[(cA0 << 2) + 2][rA0] = a_s0.z; As[(cA0 << 2) + 3][rA0] = a_s0.w;         \
    As[(cA0 << 2) + 0][rA1] = a_s1.x; As[(cA0 << 2) + 1][rA1] = a_s1.y;         \
    As[(cA0 << 2) + 2][rA1] = a_s1.z; As[(cA0 << 2) + 3][rA1] = a_s1.w;         \
    _Pragma("unroll")                                                           \
    for (int i_ = 0; i_ < 8; i_++) {                                            \
        int e_ = (i_ << 8) + tid; Bs[e_ & 31][e_ >> 5] = b_s[i_];               \
    } }

#define RC_COMPUTE() {                                                          \
    _Pragma("unroll")                                                           \
    for (int kk = 0; kk < RBK; kk++) {                                          \
        float4 av_ = *(const float4*)(&As[kk][ty << 2]);                        \
        float4 bv_ = *(const float4*)(&Bs[kk][tx << 2]);                        \
        float aa_[4] = {av_.x, av_.y, av_.z, av_.w};                            \
        float bb_[4] = {bv_.x, bv_.y, bv_.z, bv_.w};                            \
        _Pragma("unroll")                                                       \
        for (int i_ = 0; i_ < 4; i_++)                                          \
            _Pragma("unroll")                                                   \
            for (int j_ = 0; j_ < 4; j_++)                                      \
                acc[i_][j_] += aa_[i_] * bb_[j_];                               \
    } }

__global__ __launch_bounds__(256) void k_rec(const float* __restrict__ Wr, int t)
{
    __shared__ float As[RBK][RBM];
    __shared__ float Bs[RBK][RBN];
    const int tid = threadIdx.x;
    const int tx = tid & 15, ty = tid >> 4;
    const int g0 = blockIdx.x * RBN;
    const int b0 = blockIdx.y * RBM;
    const int rA0 = tid >> 3, cA0 = tid & 7, rA1 = rA0 + 32;

    float acc[4][4] = {};
    float4 a_s0, a_s1;
    float b_s[8];

    RC_LOAD(0);
    RC_STORE();
    __syncthreads();
    for (int kc = 1; kc < Hh / RBK; kc++) {
        RC_LOAD(kc);
        RC_COMPUTE();
        __syncthreads();
        RC_STORE();
        __syncthreads();
    }
    RC_COMPUTE();

#pragma unroll
    for (int i = 0; i < 4; i++) {
        int b = b0 + (ty << 2) + i;
#pragma unroll
        for (int j = 0; j < 4; j++) {
            int g = g0 + (tx << 2) + j;
            if (g < Gg)
                g_xout[b * Gg + g] = acc[i][j] + g_xk[((size_t)t * Bsz + b) * Gg + g];
        }
    }
}

// ---------------- LSTM cell + ring + local_dis + theme ----------------
__global__ __launch_bounds__(128) void k_cell(
    const float* __restrict__ Ws, const float* __restrict__ bs,
    const float* __restrict__ Wrs, const float* __restrict__ brs, int t)
{
    const int b = blockIdx.x, tid = threadIdx.x;
    __shared__ float z16[16];
    __shared__ float fm[Ll], im[Ll];
    __shared__ float thm[Hh];
    __shared__ float s64[64];
    __shared__ float ldl[KW];

    if (tid < 16) z16[tid] = g_xout[b * Gg + tid];
    __syncthreads();

    const int slot = t % KW;
    if (tid == 0) {
        float m = -1e30f;
        for (int i = 0; i < Ll; i++) m = fmaxf(m, z16[i]);
        float s[Ll], tot = 0.f;
        for (int i = 0; i < Ll; i++) { s[i] = expf(z16[i] - m); tot += s[i]; }
        float inv = 1.f / tot, cum = 0.f, msum = 0.f;
        for (int i = 0; i < Ll; i++) { cum += s[i] * inv; fm[i] = cum; msum += cum; }
        g_tmp_dis[slot * Bsz + b] = 1.f - msum * (1.f / Ll);
    }
    if (tid == 1) {
        float m = -1e30f;
        for (int i = 0; i < Ll; i++) m = fmaxf(m, z16[8 + i]);
        float s[Ll], tot = 0.f;
        for (int i = 0; i < Ll; i++) { s[i] = expf(z16[8 + i] - m); tot += s[i]; }
        float inv = 1.f / tot, cum = 0.f;
        for (int i = Ll - 1; i >= 0; i--) { cum += s[i] * inv; im[i] = cum; }
    }
    __syncthreads();

    const float* xo = &g_xout[b * Gg + 16];
    for (int e = tid; e < Hh; e += 128) {
        int l = e / CHc, j = e - l * CHc;
        float fg = sigf(xo[l * CHc + j]);
        float ig = sigf(xo[(Ll + l) * CHc + j]);
        float og = sigf(xo[(2 * Ll + l) * CHc + j]);
        float ci = tanhf(xo[(3 * Ll + l) * CHc + j]);
        float cl = g_c[b * Hh + e];
        float fmv = fm[l], imv = im[l], ovv = fmv * imv;
        float cn = ovv * (fg * cl + ig * ci) + (fmv - ovv) * cl + (imv - ovv) * ci;
        float hn = og * tanhf(cn);
        g_c[b * Hh + e] = cn;
        g_h[b * Hh + e] = hn;
        g_tmp_h[(slot * Bsz + b) * Hh + e] = hn;
    }

    if (!g_needed[t]) return;
    __syncthreads();

    if (tid == 0) {
        float d[KW], c = 0.f;
        for (int k = 0; k < KW; k++) {
            int sk = (t + 1 + k) % KW;
            c += g_tmp_dis[sk * Bsz + b];
            d[k] = c;
        }
        float m = -1e30f;
        for (int k = 0; k < KW; k++) m = fmaxf(m, d[k]);
        float tot = 0.f;
        for (int k = 0; k < KW; k++) { d[k] = expf(d[k] - m); tot += d[k]; }
        float inv = 1.f / tot;
        for (int k = 0; k < KW; k++) {
            ldl[k] = d[k] * inv;
            g_ld[b * KW + k] = ldl[k];
        }
    }
    __syncthreads();

    for (int e = tid; e < Hh; e += 128) {
        float s = 0.f;
        for (int k = 0; k < KW; k++) {
            int sk = (t + 1 + k) % KW;
            s += ldl[k] * g_tmp_h[(sk * Bsz + b) * Hh + e];
        }
        thm[e] = s * (1.f / KW);
    }
    __syncthreads();

    if (tid < 64) {
        float a = bs[tid];
        const float* w = &Ws[tid * Hh];
        for (int kk = 0; kk < Hh; kk++) a += thm[kk] * w[kk];
        s64[tid] = fmaxf(a, 0.f);
    }
    __syncthreads();

    for (int e = tid; e < Hh; e += 128) {
        float a = brs[e];
        const float* w = &Wrs[e * 64];
#pragma unroll
        for (int kk = 0; kk < 64; kk++) a += s64[kk] * w[kk];
        g_theme[b * Hh + e] = sigf(a);
    }
}

// ---------------- conv partials (only at needed steps) ----------------
#define CV_LOAD(kc_) {                                                          \
    int kb_ = (kc_) * RBK;                                                      \
    a_s0 = *(const float4*)(&A[(b0 + rA0) * Hh + kb_ + (cA0 << 2)]);            \
    a_s1 = *(const float4*)(&A[(b0 + rA1) * Hh + kb_ + (cA0 << 2)]);            \
    b_s0 = *(const float4*)(&Bm[(size_t)(kb_ + rB0) * Hh + o0 + (cB0 << 2)]);   \
    b_s1 = *(const float4*)(&Bm[(size_t)(kb_ + rB1) * Hh + o0 + (cB0 << 2)]);   \
    }

#define CV_STORE() {                                                            \
    As[(cA0 << 2) + 0][rA0] = a_s0.x; As[(cA0 << 2) + 1][rA0] = a_s0.y;         \
    As[(cA0 << 2) + 2][rA0] = a_s0.z; As[(cA0 << 2) + 3][rA0] = a_s0.w;         \
    As[(cA0 << 2) + 0][rA1] = a_s1.x; As[(cA0 << 2) + 1][rA1] = a_s1.y;         \
    As[(cA0 << 2) + 2][rA1] = a_s1.z; As[(cA0 << 2) + 3][rA1] = a_s1.w;         \
    *(float4*)(&Bs[rB0][cB0 << 2]) = b_s0;                                      \
    *(float4*)(&Bs[rB1][cB0 << 2]) = b_s1;                                      \
    }

__global__ __launch_bounds__(256) void k_conv(int t)
{
    if (!g_needed[t]) return;
    __shared__ float As[RBK][RBM];
    __shared__ float Bs[RBK][RBN];
    const int tid = threadIdx.x;
    const int tx = tid & 15, ty = tid >> 4;
    const int o0 = blockIdx.x * RBN;
    const int b0 = blockIdx.y * RBM;
    const int j = blockIdx.z;
    const int slot = (t + 1 + j) % KW;
    const float* A = g_tmp_h + (size_t)slot * Bsz * Hh;
    const float* Bm = g_Wct + (size_t)j * Hh * Hh;
    const int rA0 = tid >> 3, cA0 = tid & 7, rA1 = rA0 + 32;
    const int rB0 = tid >> 4, cB0 = tid & 15, rB1 = rB0 + 16;

    float acc[4][4] = {};
    float4 a_s0, a_s1, b_s0, b_s1;

    CV_LOAD(0);
    CV_STORE();
    __syncthreads();
    for (int kc = 1; kc < Hh / RBK; kc++) {
        CV_LOAD(kc);
        RC_COMPUTE();
        __syncthreads();
        CV_STORE();
        __syncthreads();
    }
    RC_COMPUTE();

#pragma unroll
    for (int i = 0; i < 4; i++) {
        int b = b0 + (ty << 2) + i;
#pragma unroll
        for (int jj = 0; jj < 4; jj++) {
            int o = o0 + (tx << 2) + jj;
            g_conv_part[((size_t)j * Bsz + b) * Hh + o] = acc[i][jj];
        }
    }
}

__global__ void k_reduce(const float* __restrict__ bc, int t)
{
    if (!g_needed[t]) return;
    int b = blockIdx.x, e = threadIdx.x;   // blockDim = 384
    float a = bc[e];
#pragma unroll
    for (int j = 0; j < KW; j++)
        a += g_ld[b * KW + j] * g_conv_part[((size_t)j * Bsz + b) * Hh + e];
    float r = g_h[b * Hh + e] + g_theme[b * Hh + e] * a;
    if (g_last[b] == t) g_rnn_last[b * Hh + e] = r;
}

// ---------------- final output GEMV ----------------
__global__ __launch_bounds__(128) void k_out(const float* __restrict__ bo, float* __restrict__ out)
{
    int b = blockIdx.x, o = threadIdx.x;
    __shared__ float r[Hh];
    for (int e = o; e < Hh; e += 128) r[e] = g_rnn_last[b * Hh + e];
    __syncthreads();
    float a = bo[o];
    for (int k = 0; k < Hh; k++) a += r[k] * g_Wot[k * OUTd + o];
    out[b * OUTd + o] = a;
}

// ---------------- launch: split chunks -> GEMM chunks -> scan chunks, all pipelined ----------------
// chunks chosen so the LAST scan chunk (exposed after the final GEMM) is small.
#define NCHUNKS 3
static const int c_vlo[NCHUNKS] = {0, 22, 44};
static const int c_vhi[NCHUNKS] = {22, 44, 50};

extern "C" void kernel_launch(void* const* d_in, const int* in_sizes, int n_in,
                              void* d_out, int out_size)
{
    const int*           node_ids    = (const int*)d_in[0];
    const float*         visit_times = (const float*)d_in[3];
    const unsigned char* attn_mask   = (const unsigned char*)d_in[5];
    const float*         embed       = (const float*)d_in[6];
    const float*         Wk          = (const float*)d_in[7];
    const float*         bk          = (const float*)d_in[8];
    const float*         Wr          = (const float*)d_in[9];
    const float*         br          = (const float*)d_in[10];
    const float*         Ws          = (const float*)d_in[11];
    const float*         bs          = (const float*)d_in[12];
    const float*         Wrs         = (const float*)d_in[13];
    const float*         brs         = (const float*)d_in[14];
    const float*         Wc          = (const float*)d_in[15];
    const float*         bc          = (const float*)d_in[16];
    const float*         Wo          = (const float*)d_in[17];
    const float*         bo          = (const float*)d_in[18];
    float*               out         = (float*)d_out;

    static int inited = 0;
    static cudaStream_t s2, s3;
    static cudaEvent_t evFork, evJoin, evC[NCHUNKS], evS[NCHUNKS];
    if (!inited) {
        cudaFuncSetAttribute(k_xk_mma, cudaFuncAttributeMaxDynamicSharedMemorySize, NSTG * 32768);
        cudaStreamCreateWithFlags(&s2, cudaStreamNonBlocking);
        cudaStreamCreateWithFlags(&s3, cudaStreamNonBlocking);
        cudaEventCreateWithFlags(&evFork, cudaEventDisableTiming);
        cudaEventCreateWithFlags(&evJoin, cudaEventDisableTiming);
        for (int c = 0; c < NCHUNKS; c++) {
            cudaEventCreateWithFlags(&evC[c], cudaEventDisableTiming);
            cudaEventCreateWithFlags(&evS[c], cudaEventDisableTiming);
        }
        inited = 1;
    }

    // ---- prep on primary stream (small kernels + B split) ----
    k_zero<<<512, 256>>>();
    k_last<<<Bsz, 64>>>(attn_mask);
    k_wtrans<<<512, 256>>>(Wc, Wo);
    k_wkbf<<<2048, 256>>>(Wk);

    // fork s2 (scan) and s3 (A split) from primary
    cudaEventRecord(evFork, 0);
    cudaStreamWaitEvent(s2, evFork, 0);
    cudaStreamWaitEvent(s3, evFork, 0);

    // ---- A-split chunks on s3; GEMM chunk c waits on split chunk c ----
    for (int c = 0; c < NCHUNKS; c++) {
        int t0 = c_vlo[c] * 2 * 256;                    // mi0 * 256 tiles
        int nt = (c_vhi[c] - c_vlo[c]) * 2 * 256;
        k_split_rng<<<4096, 256, 0, s3>>>(node_ids, (const float4*)embed, t0, nt);
        cudaEventRecord(evS[c], s3);
    }

    // ---- GEMM chunks on primary; gated on their split chunk; event after each ----
    for (int c = 0; c < NCHUNKS; c++) {
        cudaStreamWaitEvent(0, evS[c], 0);
        int mi0 = c_vlo[c] * 2;
        int nmt = (c_vhi[c] - c_vlo[c]) * 2;
        dim3 gx(13, nmt);
        k_xk_mma<<<gx, 256, NSTG * 32768, 0>>>(visit_times, Wk, bk, Wr, br, mi0);
        cudaEventRecord(evC[c], 0);
    }

    // ---- scan chunks on s2, each gated on its GEMM chunk ----
    for (int c = 0; c < NCHUNKS; c++) {
        cudaStreamWaitEvent(s2, evC[c], 0);
        for (int t = c_vlo[c]; t < c_vhi[c]; t++) {
            dim3 gr(25, 4);
            k_rec<<<gr, 256, 0, s2>>>(Wr, t);
            k_cell<<<Bsz, 128, 0, s2>>>(Ws, bs, Wrs, brs, t);
            dim3 gc(6, 4, KW);
            k_conv<<<gc, 256, 0, s2>>>(t);
            k_reduce<<<Bsz, Hh, 0, s2>>>(bc, t);
        }
    }
    k_out<<<Bsz, 128, 0, s2>>>(bo, out);

    // join back to primary stream
    cudaEventRecord(evJoin, s2);
    cudaStreamWaitEvent(0, evJoin, 0);
}

// round 13
// speedup vs baseline: 1.1653x; 1.1653x over previous
#include <cuda_runtime.h>
#include <cuda_fp16.h>
#include <math.h>
#include <stdint.h>

#define Bsz 256
#define Vn  50
#define Nn  64
#define Dd  128
#define NDd 8192
#define Hh  384
#define Ll  8
#define CHc 48
#define KW  10
#define OUTd 128
#define Gg  1552
#define GgPad 1664
#define Mtot 12800          /* B*V ; m = v*Bsz + b (v-major) */
#define NIT 256             /* 8192 / 32 */
#define NSTG 4              /* pipeline stages, 24KB each */
#define STGB 24576
#define WLSCALE 1024.0f

typedef unsigned long long ull;

// ---------------- device scratch (no allocs allowed) ----------------
__device__ float g_xk[(size_t)Mtot * Gg];          // [v*Bsz+b][g]
__device__ float g_xout[Bsz * Gg];
__device__ float g_h[Bsz * Hh];
__device__ float g_c[Bsz * Hh];
__device__ float g_tmp_h[KW * Bsz * Hh];
__device__ float g_tmp_dis[KW * Bsz];
__device__ float g_ld[Bsz * KW];
__device__ float g_theme[Bsz * Hh];
__device__ float g_conv_part[KW * Bsz * Hh];
__device__ float g_rnn_last[Bsz * Hh];
__device__ float g_Wct[KW * Hh * Hh];
__device__ float g_Wot[Hh * OUTd];
__device__ int   g_last[Bsz];
__device__ int   g_needed[64];
// pre-tiled, pre-swizzled 8KB tiles: [tileIdx*256 + ck] * 4096 fp16 elems
// phys within tile: row*64 + ((ch ^ ((row>>1)&3))<<4) + byte_in_16B
__device__ __align__(256) __half g_Wk_h[(size_t)GgPad * NDd];   // fp16 hi
__device__ __align__(256) __half g_Wk_l[(size_t)GgPad * NDd];   // fp16 residual * 1024
__device__ __align__(256) __half g_A_h[(size_t)Mtot * NDd];     // fp16 (no split)

__device__ __forceinline__ float sigf(float x) { return 1.0f / (1.0f + expf(-x)); }

__device__ __forceinline__ uint32_t smem_u32(const void* p) {
    uint32_t a;
    asm("{ .reg .u64 t; cvta.to.shared.u64 t, %1; cvt.u32.u64 %0, t; }" : "=r"(a) : "l"(p));
    return a;
}

// ---------------- sm_90-era async + sm_80 tensor path (valid under .target sm_103) ----------------
__device__ __forceinline__ void ldm4(uint32_t* r, uint32_t addr) {
    asm volatile("ldmatrix.sync.aligned.m8n8.x4.shared.b16 {%0,%1,%2,%3}, [%4];"
                 : "=r"(r[0]), "=r"(r[1]), "=r"(r[2]), "=r"(r[3]) : "r"(addr));
}
__device__ __forceinline__ void mma16816h(float* c, const uint32_t* a, const uint32_t* b) {
    asm volatile("mma.sync.aligned.m16n8k16.row.col.f32.f16.f16.f32 "
                 "{%0,%1,%2,%3}, {%4,%5,%6,%7}, {%8,%9}, {%0,%1,%2,%3};"
                 : "+f"(c[0]), "+f"(c[1]), "+f"(c[2]), "+f"(c[3])
                 : "r"(a[0]), "r"(a[1]), "r"(a[2]), "r"(a[3]), "r"(b[0]), "r"(b[1]));
}

#define MB_INIT(a, c) \
    asm volatile("mbarrier.init.shared.b64 [%0], %1;" :: "r"((uint32_t)(a)), "r"((uint32_t)(c)) : "memory")
#define MB_EXPECT(a, tx) \
    asm volatile("mbarrier.arrive.expect_tx.shared.b64 _, [%0], %1;" :: "r"((uint32_t)(a)), "r"((uint32_t)(tx)) : "memory")
#define MB_WAIT(a, par) do {                                                       \
    uint32_t _m = (uint32_t)(a), _p = (uint32_t)(par), _d;                         \
    asm volatile("{\n\t.reg .pred p;\n\t"                                          \
        "mbarrier.try_wait.parity.shared.b64 p, [%1], %2;\n\t"                     \
        "selp.b32 %0, 1, 0, p;\n\t}" : "=r"(_d) : "r"(_m), "r"(_p) : "memory");    \
    if (!_d) {                                                                     \
        asm volatile("{\n\t.reg .pred P1;\n\t"                                     \
        "WL_%=:\n\t"                                                               \
        "mbarrier.try_wait.parity.shared.b64 P1, [%0], %1;\n\t"                    \
        "@P1 bra.uni WD_%=;\n\t"                                                   \
        "bra.uni WL_%=;\n\t"                                                       \
        "WD_%=:\n\t}" :: "r"(_m), "r"(_p) : "memory");                             \
    } } while (0)
#define FENCE_ASYNC() asm volatile("fence.proxy.async.shared::cta;" ::: "memory")
#define BULK_G2S(dst, src, sz, mbar) \
    asm volatile("cp.async.bulk.shared::cta.global.mbarrier::complete_tx::bytes [%0], [%1], %2, [%3];" \
        :: "r"((uint32_t)(dst)), "l"(__cvta_generic_to_global(src)), "r"((uint32_t)(sz)), "r"((uint32_t)(mbar)) : "memory")

// ---------------- small init kernels ----------------
__global__ void k_zero() {
    int i = blockIdx.x * blockDim.x + threadIdx.x;
    int st = gridDim.x * blockDim.x;
    for (int k = i; k < KW * Bsz * Hh; k += st) g_tmp_h[k] = 0.f;
    for (int k = i; k < Bsz * Hh; k += st) { g_c[k] = 0.f; g_h[k] = 0.f; }
    for (int k = i; k < KW * Bsz; k += st) g_tmp_dis[k] = 0.f;
    if (i < 64) g_needed[i] = 0;
}

__global__ void k_last(const unsigned char* __restrict__ mask) {
    int b = blockIdx.x, v = threadIdx.x;   // blockDim = 64
    __shared__ int nv[64];
    int val = 0;
    if (v < Vn) {
        const unsigned char* mp = mask + ((size_t)b * Vn + v) * Nn;
        int allp = 1;
        for (int n = 0; n < Nn; n++) allp &= (mp[n] != 0);
        val = allp ? 0 : 1;
    }
    nv[v] = val;
    __syncthreads();
    if (v == 0) {
        int c = 0;
        for (int i = 0; i < Vn; i++) c += nv[i];
        int last = c - 1;
        if (last < 0) last += Vn;
        g_last[b] = last;
        g_needed[last] = 1;
    }
}

__global__ void k_wtrans(const float* __restrict__ Wc, const float* __restrict__ Wo) {
    int i = blockIdx.x * blockDim.x + threadIdx.x;
    int st = gridDim.x * blockDim.x;
    for (int idx = i; idx < Hh * Hh * KW; idx += st) {
        int o = idx / (Hh * KW);
        int rem = idx - o * (Hh * KW);
        int h = rem / KW;
        int j = rem - h * KW;
        g_Wct[((size_t)j * Hh + h) * Hh + o] = Wc[idx];
    }
    for (int idx = i; idx < OUTd * Hh; idx += st) {
        int o = idx / Hh, k = idx - o * Hh;
        g_Wot[k * OUTd + o] = Wo[idx];
    }
}

// decode physical element-group position -> (tileRow, logical k-chunk elem)
// e4 = group of 4 fp16 (8 bytes). byte off in tile = (e4*8)&8191.
__device__ __forceinline__ void dec_tile(size_t e4, int& tile, int& row, int& kk) {
    tile = (int)(e4 >> 10);                    // 1024 groups per 8KB tile
    int off = ((int)e4 & 1023) * 8;            // byte offset in tile
    row = off >> 6;
    int w = off & 63;
    int chp = w >> 4;
    int ch = chp ^ ((row >> 1) & 3);
    kk = ch * 8 + ((w & 15) >> 1);             // 0..28, step 4
}

__device__ __forceinline__ uint32_t pkh(__half a, __half b) {
    __half2 t; t.x = a; t.y = b;
    return *(uint32_t*)&t;
}

// split Wk[:, :8192] into fp16 hi + scaled-residual tiles [ni*256+ck] (GgPad rows, zero pad)
__global__ void k_wkbf(const float* __restrict__ Wk) {
    size_t i = (size_t)blockIdx.x * blockDim.x + threadIdx.x;
    size_t st = (size_t)gridDim.x * blockDim.x;
    const size_t TOT4 = (size_t)GgPad * NDd / 4;
    uint2* ph = (uint2*)g_Wk_h;
    uint2* pl = (uint2*)g_Wk_l;
    for (size_t e4 = i; e4 < TOT4; e4 += st) {
        int tile, row, kk;
        dec_tile(e4, tile, row, kk);
        int ni = tile >> 8, ck = tile & 255;
        int g = ni * 128 + row;
        int k = ck * 32 + kk;
        float v0 = 0.f, v1 = 0.f, v2 = 0.f, v3 = 0.f;
        if (g < Gg) {
            const float* wr = Wk + (size_t)g * (NDd + 1) + k;
            v0 = wr[0]; v1 = wr[1]; v2 = wr[2]; v3 = wr[3];
        }
        __half h0 = __float2half_rn(v0), h1 = __float2half_rn(v1),
               h2 = __float2half_rn(v2), h3 = __float2half_rn(v3);
        __half l0 = __float2half_rn((v0 - __half2float(h0)) * WLSCALE);
        __half l1 = __float2half_rn((v1 - __half2float(h1)) * WLSCALE);
        __half l2 = __float2half_rn((v2 - __half2float(h2)) * WLSCALE);
        __half l3 = __float2half_rn((v3 - __half2float(h3)) * WLSCALE);
        ph[e4] = make_uint2(pkh(h0, h1), pkh(h2, h3));
        pl[e4] = make_uint2(pkh(l0, l1), pkh(l2, l3));
    }
}

// gather x = embed[node_ids] -> fp16 tiles [mi*256+ck]; m = v*Bsz+b
// processes tile range [tile0, tile0+ntiles) so chunks can pipeline with the GEMM
__global__ void k_split_rng(const int* __restrict__ ids, const float4* __restrict__ ef4,
                            int tile0, int ntiles) {
    size_t i = (size_t)blockIdx.x * blockDim.x + threadIdx.x;
    size_t st = (size_t)gridDim.x * blockDim.x;
    const size_t base = (size_t)tile0 << 10;
    const size_t CNT4 = (size_t)ntiles << 10;
    uint2* ph = (uint2*)g_A_h;
    for (size_t r = i; r < CNT4; r += st) {
        size_t e4 = base + r;
        int tile, row, kk;
        dec_tile(e4, tile, row, kk);
        int mi = tile >> 8, ck = tile & 255;
        int m = mi * 128 + row;
        int k = ck * 32 + kk;
        int v_ = m >> 8, b = m & 255;
        int id = __ldg(&ids[(b * Vn + v_) * Nn + (k >> 7)]);
        float4 v = __ldg(&ef4[(size_t)id * 32 + ((k & 127) >> 2)]);
        ph[e4] = make_uint2(pkh(__float2half_rn(v.x), __float2half_rn(v.y)),
                            pkh(__float2half_rn(v.z), __float2half_rn(v.w)));
    }
}

// ---------------- tensor-core input projection: bulk-TMA loader + fp16 mma.sync ----------------
// XK[m,g] = sum_d x[m,d]*Wk[g,d] + (bk+br)[g] + vt[m]*(Wk[g,ND]+Wr[g,H])
// fp16 2-pass: D = a_h*w_h (acc1) + a_h*(w_l*1024) (acc2); epilogue acc1 + acc2/1024.
// smem per stage 24KB: A[8K] Wh[8K] Wl[8K]; NSTG=4 stages = 96KB dynamic.
// loader: 3x cp.async.bulk (8KB each) per iter issued by thread 0, mbarrier completion.

__global__ __launch_bounds__(256, 1)
void k_xk_mma(const float* __restrict__ vt, const float* __restrict__ Wk,
              const float* __restrict__ bk, const float* __restrict__ Wr,
              const float* __restrict__ br, int mi0)
{
    extern __shared__ char dsm[];
    __shared__ float bias_s[128], wl_s[128], vt_s[128];
    __shared__ __align__(8) ull mbars[NSTG];
    const uint32_t smb = smem_u32(dsm);
    const int tid = threadIdx.x;
    const int wid = tid >> 5, lane = tid & 31;
    const int wm = wid & 1, wn = wid >> 1;    // warp tile: 64 rows x 32 cols

    const int mi = mi0 + blockIdx.y;          // m-tile (128 v-major rows)
    const int ni = blockIdx.x;
    const int m0 = mi * 128, n0 = ni * 128;

    if (tid < NSTG) MB_INIT(smem_u32(&mbars[tid]), 1);
    if (tid < 128) {
        int g = n0 + tid;
        if (g < Gg) {
            bias_s[tid] = bk[g] + br[g];
            wl_s[tid] = Wk[(size_t)g * (NDd + 1) + NDd] + Wr[(size_t)g * (Hh + 1) + Hh];
        } else { bias_s[tid] = 0.f; wl_s[tid] = 0.f; }
        int m = m0 + tid;
        int v_ = m >> 8, b = m & 255;
        vt_s[tid] = __ldg(&vt[b * Vn + v_]);
    }
    FENCE_ASYNC();
    __syncthreads();

    float acc1[4][4][4], acc2[4][4][4];
#pragma unroll
    for (int a = 0; a < 4; a++)
#pragma unroll
        for (int b = 0; b < 4; b++)
#pragma unroll
            for (int c = 0; c < 4; c++) { acc1[a][b][c] = 0.f; acc2[a][b][c] = 0.f; }

    // prologue: fill NSTG-1 stages
    if (tid == 0) {
#pragma unroll
        for (int s = 0; s < NSTG - 1; s++) {
            uint32_t mb = smem_u32(&mbars[s]);
            uint32_t so = smb + s * STGB;
            size_t at = ((size_t)mi * 256 + s) * 4096;
            size_t bt = ((size_t)ni * 256 + s) * 4096;
            MB_EXPECT(mb, (uint32_t)STGB);
            BULK_G2S(so,         g_A_h  + at, 8192u, mb);
            BULK_G2S(so + 8192,  g_Wk_h + bt, 8192u, mb);
            BULK_G2S(so + 16384, g_Wk_l + bt, 8192u, mb);
        }
    }

    for (int ck = 0; ck < NIT; ck++) {
        const int st = ck & (NSTG - 1);
        MB_WAIT(smem_u32(&mbars[st]), (ck >> 2) & 1);

        uint32_t so = smb + st * STGB;
#pragma unroll
        for (int kc = 0; kc < 2; kc++) {
            uint32_t a_f[4][4], b_hi[4][2], b_lo[4][2];
            const int arow = wm * 64 + (lane & 15);
            const int ach = 2 * kc + (lane >> 4);
#pragma unroll
            for (int mt = 0; mt < 4; mt++) {
                int r = arow + mt * 16;
                uint32_t ph = (uint32_t)(r * 64 + ((ach ^ ((r >> 1) & 3)) << 4));
                ldm4(a_f[mt], so + ph);
            }
            const int brow = wn * 32 + ((lane >> 4) & 1) * 8 + (lane & 7);
            const int bch = 2 * kc + ((lane >> 3) & 1);
#pragma unroll
            for (int np = 0; np < 2; np++) {
                int r = brow + np * 16;
                uint32_t ph = (uint32_t)(r * 64 + ((bch ^ ((r >> 1) & 3)) << 4));
                uint32_t t[4];
                ldm4(t, so + 8192 + ph);
                b_hi[np * 2][0] = t[0]; b_hi[np * 2][1] = t[1];
                b_hi[np * 2 + 1][0] = t[2]; b_hi[np * 2 + 1][1] = t[3];
                ldm4(t, so + 16384 + ph);
                b_lo[np * 2][0] = t[0]; b_lo[np * 2][1] = t[1];
                b_lo[np * 2 + 1][0] = t[2]; b_lo[np * 2 + 1][1] = t[3];
            }
#pragma unroll
            for (int mt = 0; mt < 4; mt++)
#pragma unroll
                for (int nt = 0; nt < 4; nt++) mma16816h(acc1[mt][nt], a_f[mt], b_hi[nt]);
#pragma unroll
            for (int mt = 0; mt < 4; mt++)
#pragma unroll
                for (int nt = 0; nt < 4; nt++) mma16816h(acc2[mt][nt], a_f[mt], b_lo[nt]);
        }
        __syncthreads();   // all threads done reading stage st
        if (tid == 0 && ck + NSTG - 1 < NIT) {
            int nk = ck + NSTG - 1;
            int ns = nk & (NSTG - 1);          // freed by barrier above
            uint32_t mb = smem_u32(&mbars[ns]);
            uint32_t nso = smb + ns * STGB;
            size_t at = ((size_t)mi * 256 + nk) * 4096;
            size_t bt = ((size_t)ni * 256 + nk) * 4096;
            MB_EXPECT(mb, (uint32_t)STGB);
            BULK_G2S(nso,         g_A_h  + at, 8192u, mb);
            BULK_G2S(nso + 8192,  g_Wk_h + bt, 8192u, mb);
            BULK_G2S(nso + 16384, g_Wk_l + bt, 8192u, mb);
        }
    }

    // epilogue: combine scaled correction, fold bias + interval term
    const float inv_s = 1.0f / WLSCALE;
#pragma unroll
    for (int mt = 0; mt < 4; mt++) {
        int rl0 = wm * 64 + mt * 16 + (lane >> 2);
        int rl1 = rl0 + 8;
        float v0 = vt_s[rl0], v1 = vt_s[rl1];
        size_t ro0 = (size_t)(m0 + rl0) * Gg;
        size_t ro1 = (size_t)(m0 + rl1) * Gg;
#pragma unroll
        for (int nt = 0; nt < 4; nt++) {
            int gl = wn * 32 + nt * 8 + (lane & 3) * 2;
            int g = n0 + gl;
            if (g < Gg) {
                g_xk[ro0 + g] = acc1[mt][nt][0] + acc2[mt][nt][0] * inv_s + bias_s[gl] + v0 * wl_s[gl];
                g_xk[ro1 + g] = acc1[mt][nt][2] + acc2[mt][nt][2] * inv_s + bias_s[gl] + v1 * wl_s[gl];
            }
            if (g + 1 < Gg) {
                g_xk[ro0 + g + 1] = acc1[mt][nt][1] + acc2[mt][nt][1] * inv_s + bias_s[gl + 1] + v0 * wl_s[gl + 1];
                g_xk[ro1 + g + 1] = acc1[mt][nt][3] + acc2[mt][nt][3] * inv_s + bias_s[gl + 1] + v1 * wl_s[gl + 1];
            }
        }
    }
}

// ---------------- recurrent GEMM: xout = XK[t*Bsz+b] + h @ Wr[:, :H].T ----------------
#define RBM 64
#define RBN 64
#define RBK 32

#define RC_LOAD(kc_) {                                                          \
    int kb_ = (kc_) * RBK;                                                      \
    a_s0 = *(const float4*)(&g_h[(b0 + rA0) * Hh + kb_ + (cA0 << 2)]);          \
    a_s1 = *(const float4*)(&g_h[(b0 + rA1) * Hh + kb_ + (cA0 << 2)]);          \
    _Pragma("unroll")                                                           \
    for (int i_ = 0; i_ < 8; i_++) {                                            \
        int e_ = (i_ << 8) + tid; int kl_ = e_ & 31, gl_ = e_ >> 5;             \
        int g_ = g0 + gl_;                                                      \
        b_s[i_] = (g_ < Gg) ? Wr[(size_t)g_ * (Hh + 1) + kb_ + kl_] : 0.f;      \
    } }

#define RC_STORE() {                                                            \
    As[(cA0 << 2) + 0][rA0] = a_s0.x; As[(cA0 << 2) + 1][rA0] = a_s0.y;         \
    As[(cA0 << 2) + 2][rA0] = a_s0.z; As[(cA0 << 2) + 3][rA0] = a_s0.w;         \
    As[(cA0 << 2) + 0][rA1] = a_s1.x; As[(cA0 << 2) + 1][rA1] = a_s1.y;         \
    As[(cA0 << 2) + 2][rA1] = a_s1.z; As[(cA0 << 2) + 3][rA1] = a_s1.w;         \
    _Pragma("unroll")                                                           \
    for (int i_ = 0; i_ < 8; i_++) {                                            \
        int e_ = (i_ << 8) + tid; Bs[e_ & 31][e_ >> 5] = b_s[i_];               \
    } }

#define RC_COMPUTE() {                                                          \
    _Pragma("unroll")                                                           \
    for (int kk = 0; kk < RBK; kk++) {                                          \
        float4 av_ = *(const float4*)(&As[kk][ty << 2]);                        \
        float4 bv_ = *(const float4*)(&Bs[kk][tx << 2]);                        \
        float aa_[4] = {av_.x, av_.y, av_.z, av_.w};                            \
        float bb_[4] = {bv_.x, bv_.y, bv_.z, bv_.w};                            \
        _Pragma("unroll")                                                       \
        for (int i_ = 0; i_ < 4; i_++)                                          \
            _Pragma("unroll")                                                   \
            for (int j_ = 0; j_ < 4; j_++)                                      \
                acc[i_][j_] += aa_[i_] * bb_[j_];                               \
    } }

__global__ __launch_bounds__(256) void k_rec(const float* __restrict__ Wr, int t)
{
    __shared__ float As[RBK][RBM];
    __shared__ float Bs[RBK][RBN];
    const int tid = threadIdx.x;
    const int tx = tid & 15, ty = tid >> 4;
    const int g0 = blockIdx.x * RBN;
    const int b0 = blockIdx.y * RBM;
    const int rA0 = tid >> 3, cA0 = tid & 7, rA1 = rA0 + 32;

    float acc[4][4] = {};
    float4 a_s0, a_s1;
    float b_s[8];

    RC_LOAD(0);
    RC_STORE();
    __syncthreads();
    for (int kc = 1; kc < Hh / RBK; kc++) {
        RC_LOAD(kc);
        RC_COMPUTE();
        __syncthreads();
        RC_STORE();
        __syncthreads();
    }
    RC_COMPUTE();

#pragma unroll
    for (int i = 0; i < 4; i++) {
        int b = b0 + (ty << 2) + i;
#pragma unroll
        for (int j = 0; j < 4; j++) {
            int g = g0 + (tx << 2) + j;
            if (g < Gg)
                g_xout[b * Gg + g] = acc[i][j] + g_xk[((size_t)t * Bsz + b) * Gg + g];
        }
    }
}

// ---------------- LSTM cell + ring + local_dis + theme ----------------
__global__ __launch_bounds__(128) void k_cell(
    const float* __restrict__ Ws, const float* __restrict__ bs,
    const float* __restrict__ Wrs, const float* __restrict__ brs, int t)
{
    const int b = blockIdx.x, tid = threadIdx.x;
    __shared__ float z16[16];
    __shared__ float fm[Ll], im[Ll];
    __shared__ float thm[Hh];
    __shared__ float s64[64];
    __shared__ float ldl[KW];

    if (tid < 16) z16[tid] = g_xout[b * Gg + tid];
    __syncthreads();

    const int slot = t % KW;
    if (tid == 0) {
        float m = -1e30f;
        for (int i = 0; i < Ll; i++) m = fmaxf(m, z16[i]);
        float s[Ll], tot = 0.f;
        for (int i = 0; i < Ll; i++) { s[i] = expf(z16[i] - m); tot += s[i]; }
        float inv = 1.f / tot, cum = 0.f, msum = 0.f;
        for (int i = 0; i < Ll; i++) { cum += s[i] * inv; fm[i] = cum; msum += cum; }
        g_tmp_dis[slot * Bsz + b] = 1.f - msum * (1.f / Ll);
    }
    if (tid == 1) {
        float m = -1e30f;
        for (int i = 0; i < Ll; i++) m = fmaxf(m, z16[8 + i]);
        float s[Ll], tot = 0.f;
        for (int i = 0; i < Ll; i++) { s[i] = expf(z16[8 + i] - m); tot += s[i]; }
        float inv = 1.f / tot, cum = 0.f;
        for (int i = Ll - 1; i >= 0; i--) { cum += s[i] * inv; im[i] = cum; }
    }
    __syncthreads();

    const float* xo = &g_xout[b * Gg + 16];
    for (int e = tid; e < Hh; e += 128) {
        int l = e / CHc, j = e - l * CHc;
        float fg = sigf(xo[l * CHc + j]);
        float ig = sigf(xo[(Ll + l) * CHc + j]);
        float og = sigf(xo[(2 * Ll + l) * CHc + j]);
        float ci = tanhf(xo[(3 * Ll + l) * CHc + j]);
        float cl = g_c[b * Hh + e];
        float fmv = fm[l], imv = im[l], ovv = fmv * imv;
        float cn = ovv * (fg * cl + ig * ci) + (fmv - ovv) * cl + (imv - ovv) * ci;
        float hn = og * tanhf(cn);
        g_c[b * Hh + e] = cn;
        g_h[b * Hh + e] = hn;
        g_tmp_h[(slot * Bsz + b) * Hh + e] = hn;
    }

    if (!g_needed[t]) return;
    __syncthreads();

    if (tid == 0) {
        float d[KW], c = 0.f;
        for (int k = 0; k < KW; k++) {
            int sk = (t + 1 + k) % KW;
            c += g_tmp_dis[sk * Bsz + b];
            d[k] = c;
        }
        float m = -1e30f;
        for (int k = 0; k < KW; k++) m = fmaxf(m, d[k]);
        float tot = 0.f;
        for (int k = 0; k < KW; k++) { d[k] = expf(d[k] - m); tot += d[k]; }
        float inv = 1.f / tot;
        for (int k = 0; k < KW; k++) {
            ldl[k] = d[k] * inv;
            g_ld[b * KW + k] = ldl[k];
        }
    }
    __syncthreads();

    for (int e = tid; e < Hh; e += 128) {
        float s = 0.f;
        for (int k = 0; k < KW; k++) {
            int sk = (t + 1 + k) % KW;
            s += ldl[k] * g_tmp_h[(sk * Bsz + b) * Hh + e];
        }
        thm[e] = s * (1.f / KW);
    }
    __syncthreads();

    if (tid < 64) {
        float a = bs[tid];
        const float* w = &Ws[tid * Hh];
        for (int kk = 0; kk < Hh; kk++) a += thm[kk] * w[kk];
        s64[tid] = fmaxf(a, 0.f);
    }
    __syncthreads();

    for (int e = tid; e < Hh; e += 128) {
        float a = brs[e];
        const float* w = &Wrs[e * 64];
#pragma unroll
        for (int kk = 0; kk < 64; kk++) a += s64[kk] * w[kk];
        g_theme[b * Hh + e] = sigf(a);
    }
}

// ---------------- conv partials (only at needed steps) ----------------
#define CV_LOAD(kc_) {                                                          \
    int kb_ = (kc_) * RBK;                                                      \
    a_s0 = *(const float4*)(&A[(b0 + rA0) * Hh + kb_ + (cA0 << 2)]);            \
    a_s1 = *(const float4*)(&A[(b0 + rA1) * Hh + kb_ + (cA0 << 2)]);            \
    b_s0 = *(const float4*)(&Bm[(size_t)(kb_ + rB0) * Hh + o0 + (cB0 << 2)]);   \
    b_s1 = *(const float4*)(&Bm[(size_t)(kb_ + rB1) * Hh + o0 + (cB0 << 2)]);   \
    }

#define CV_STORE() {                                                            \
    As[(cA0 << 2) + 0][rA0] = a_s0.x; As[(cA0 << 2) + 1][rA0] = a_s0.y;         \
    As[(cA0 << 2) + 2][rA0] = a_s0.z; As[(cA0 << 2) + 3][rA0] = a_s0.w;         \
    As[(cA0 << 2) + 0][rA1] = a_s1.x; As[(cA0 << 2) + 1][rA1] = a_s1.y;         \
    As[(cA0 << 2) + 2][rA1] = a_s1.z; As[(cA0 << 2) + 3][rA1] = a_s1.w;         \
    *(float4*)(&Bs[rB0][cB0 << 2]) = b_s0;                                      \
    *(float4*)(&Bs[rB1][cB0 << 2]) = b_s1;                                      \
    }

__global__ __launch_bounds__(256) void k_conv(int t)
{
    if (!g_needed[t]) return;
    __shared__ float As[RBK][RBM];
    __shared__ float Bs[RBK][RBN];
    const int tid = threadIdx.x;
    const int tx = tid & 15, ty = tid >> 4;
    const int o0 = blockIdx.x * RBN;
    const int b0 = blockIdx.y * RBM;
    const int j = blockIdx.z;
    const int slot = (t + 1 + j) % KW;
    const float* A = g_tmp_h + (size_t)slot * Bsz * Hh;
    const float* Bm = g_Wct + (size_t)j * Hh * Hh;
    const int rA0 = tid >> 3, cA0 = tid & 7, rA1 = rA0 + 32;
    const int rB0 = tid >> 4, cB0 = tid & 15, rB1 = rB0 + 16;

    float acc[4][4] = {};
    float4 a_s0, a_s1, b_s0, b_s1;

    CV_LOAD(0);
    CV_STORE();
    __syncthreads();
    for (int kc = 1; kc < Hh / RBK; kc++) {
        CV_LOAD(kc);
        RC_COMPUTE();
        __syncthreads();
        CV_STORE();
        __syncthreads();
    }
    RC_COMPUTE();

#pragma unroll
    for (int i = 0; i < 4; i++) {
        int b = b0 + (ty << 2) + i;
#pragma unroll
        for (int jj = 0; jj < 4; jj++) {
            int o = o0 + (tx << 2) + jj;
            g_conv_part[((size_t)j * Bsz + b) * Hh + o] = acc[i][jj];
        }
    }
}

__global__ void k_reduce(const float* __restrict__ bc, int t)
{
    if (!g_needed[t]) return;
    int b = blockIdx.x, e = threadIdx.x;   // blockDim = 384
    float a = bc[e];
#pragma unroll
    for (int j = 0; j < KW; j++)
        a += g_ld[b * KW + j] * g_conv_part[((size_t)j * Bsz + b) * Hh + e];
    float r = g_h[b * Hh + e] + g_theme[b * Hh + e] * a;
    if (g_last[b] == t) g_rnn_last[b * Hh + e] = r;
}

// ---------------- final output GEMV ----------------
__global__ __launch_bounds__(128) void k_out(const float* __restrict__ bo, float* __restrict__ out)
{
    int b = blockIdx.x, o = threadIdx.x;
    __shared__ float r[Hh];
    for (int e = o; e < Hh; e += 128) r[e] = g_rnn_last[b * Hh + e];
    __syncthreads();
    float a = bo[o];
    for (int k = 0; k < Hh; k++) a += r[k] * g_Wot[k * OUTd + o];
    out[b * OUTd + o] = a;
}

// ---------------- launch: split chunks -> GEMM chunks -> scan chunks, all pipelined ----------------
#define NCHUNKS 3
static const int c_vlo[NCHUNKS] = {0, 22, 44};
static const int c_vhi[NCHUNKS] = {22, 44, 50};

extern "C" void kernel_launch(void* const* d_in, const int* in_sizes, int n_in,
                              void* d_out, int out_size)
{
    const int*           node_ids    = (const int*)d_in[0];
    const float*         visit_times = (const float*)d_in[3];
    const unsigned char* attn_mask   = (const unsigned char*)d_in[5];
    const float*         embed       = (const float*)d_in[6];
    const float*         Wk          = (const float*)d_in[7];
    const float*         bk          = (const float*)d_in[8];
    const float*         Wr          = (const float*)d_in[9];
    const float*         br          = (const float*)d_in[10];
    const float*         Ws          = (const float*)d_in[11];
    const float*         bs          = (const float*)d_in[12];
    const float*         Wrs         = (const float*)d_in[13];
    const float*         brs         = (const float*)d_in[14];
    const float*         Wc          = (const float*)d_in[15];
    const float*         bc          = (const float*)d_in[16];
    const float*         Wo          = (const float*)d_in[17];
    const float*         bo          = (const float*)d_in[18];
    float*               out         = (float*)d_out;

    static int inited = 0;
    static cudaStream_t s2, s3;
    static cudaEvent_t evFork, evJoin, evC[NCHUNKS], evS[NCHUNKS];
    if (!inited) {
        cudaFuncSetAttribute(k_xk_mma, cudaFuncAttributeMaxDynamicSharedMemorySize, NSTG * STGB);
        cudaStreamCreateWithFlags(&s2, cudaStreamNonBlocking);
        cudaStreamCreateWithFlags(&s3, cudaStreamNonBlocking);
        cudaEventCreateWithFlags(&evFork, cudaEventDisableTiming);
        cudaEventCreateWithFlags(&evJoin, cudaEventDisableTiming);
        for (int c = 0; c < NCHUNKS; c++) {
            cudaEventCreateWithFlags(&evC[c], cudaEventDisableTiming);
            cudaEventCreateWithFlags(&evS[c], cudaEventDisableTiming);
        }
        inited = 1;
    }

    // ---- prep on primary stream (small kernels + W split) ----
    k_zero<<<512, 256>>>();
    k_last<<<Bsz, 64>>>(attn_mask);
    k_wtrans<<<512, 256>>>(Wc, Wo);
    k_wkbf<<<2048, 256>>>(Wk);

    // fork s2 (scan) and s3 (A split) from primary
    cudaEventRecord(evFork, 0);
    cudaStreamWaitEvent(s2, evFork, 0);
    cudaStreamWaitEvent(s3, evFork, 0);

    // ---- A-split chunks on s3; GEMM chunk c waits on split chunk c ----
    for (int c = 0; c < NCHUNKS; c++) {
        int t0 = c_vlo[c] * 2 * 256;                    // mi0 * 256 tiles
        int nt = (c_vhi[c] - c_vlo[c]) * 2 * 256;
        k_split_rng<<<4096, 256, 0, s3>>>(node_ids, (const float4*)embed, t0, nt);
        cudaEventRecord(evS[c], s3);
    }

    // ---- GEMM chunks on primary; gated on their split chunk; event after each ----
    for (int c = 0; c < NCHUNKS; c++) {
        cudaStreamWaitEvent(0, evS[c], 0);
        int mi0 = c_vlo[c] * 2;
        int nmt = (c_vhi[c] - c_vlo[c]) * 2;
        dim3 gx(13, nmt);
        k_xk_mma<<<gx, 256, NSTG * STGB, 0>>>(visit_times, Wk, bk, Wr, br, mi0);
        cudaEventRecord(evC[c], 0);
    }

    // ---- scan chunks on s2, each gated on its GEMM chunk ----
    for (int c = 0; c < NCHUNKS; c++) {
        cudaStreamWaitEvent(s2, evC[c], 0);
        for (int t = c_vlo[c]; t < c_vhi[c]; t++) {
            dim3 gr(25, 4);
            k_rec<<<gr, 256, 0, s2>>>(Wr, t);
            k_cell<<<Bsz, 128, 0, s2>>>(Ws, bs, Wrs, brs, t);
            dim3 gc(6, 4, KW);
            k_conv<<<gc, 256, 0, s2>>>(t);
            k_reduce<<<Bsz, Hh, 0, s2>>>(bc, t);
        }
    }
    k_out<<<Bsz, 128, 0, s2>>>(bo, out);

    // join back to primary stream
    cudaEventRecord(evJoin, s2);
    cudaStreamWaitEvent(0, evJoin, 0);
}

// round 14
// speedup vs baseline: 1.4567x; 1.2501x over previous
#include <cuda_runtime.h>
#include <cuda_fp16.h>
#include <math.h>
#include <stdint.h>

#define Bsz 256
#define Vn  50
#define Nn  64
#define Dd  128
#define NDd 8192
#define Hh  384
#define Ll  8
#define CHc 48
#define KW  10
#define OUTd 128
#define Gg  1552
#define GgPad 1664
#define Mtot 12800          /* B*V ; m = v*Bsz + b (v-major) */
#define NIT 256             /* 8192 / 32 */
#define NSTG 4              /* pipeline stages, 16KB each */
#define STGB 16384

typedef unsigned long long ull;

// ---------------- device scratch (no allocs allowed) ----------------
__device__ float g_xk[(size_t)Mtot * Gg];          // [v*Bsz+b][g]
__device__ float g_xout[Bsz * Gg];
__device__ float g_h[Bsz * Hh];
__device__ float g_c[Bsz * Hh];
__device__ float g_tmp_h[KW * Bsz * Hh];
__device__ float g_tmp_dis[KW * Bsz];
__device__ float g_ld[Bsz * KW];
__device__ float g_theme[Bsz * Hh];
__device__ float g_conv_part[KW * Bsz * Hh];
__device__ float g_rnn_last[Bsz * Hh];
__device__ float g_Wct[KW * Hh * Hh];
__device__ float g_Wot[Hh * OUTd];
__device__ int   g_last[Bsz];
__device__ int   g_needed[64];
// pre-tiled, pre-swizzled 8KB tiles: [tileIdx*256 + ck] * 4096 fp16 elems
// phys within tile: row*64 + ((ch ^ ((row>>1)&3))<<4) + byte_in_16B
__device__ __align__(256) __half g_Wk_h[(size_t)GgPad * NDd];   // fp16
__device__ __align__(256) __half g_A_h[(size_t)Mtot * NDd];     // fp16

__device__ __forceinline__ float sigf(float x) { return 1.0f / (1.0f + expf(-x)); }

__device__ __forceinline__ uint32_t smem_u32(const void* p) {
    uint32_t a;
    asm("{ .reg .u64 t; cvta.to.shared.u64 t, %1; cvt.u32.u64 %0, t; }" : "=r"(a) : "l"(p));
    return a;
}

// ---------------- sm_90-era async + sm_80 tensor path (valid under .target sm_103) ----------------
__device__ __forceinline__ void ldm4(uint32_t* r, uint32_t addr) {
    asm volatile("ldmatrix.sync.aligned.m8n8.x4.shared.b16 {%0,%1,%2,%3}, [%4];"
                 : "=r"(r[0]), "=r"(r[1]), "=r"(r[2]), "=r"(r[3]) : "r"(addr));
}
__device__ __forceinline__ void mma16816h(float* c, const uint32_t* a, const uint32_t* b) {
    asm volatile("mma.sync.aligned.m16n8k16.row.col.f32.f16.f16.f32 "
                 "{%0,%1,%2,%3}, {%4,%5,%6,%7}, {%8,%9}, {%0,%1,%2,%3};"
                 : "+f"(c[0]), "+f"(c[1]), "+f"(c[2]), "+f"(c[3])
                 : "r"(a[0]), "r"(a[1]), "r"(a[2]), "r"(a[3]), "r"(b[0]), "r"(b[1]));
}

#define MB_INIT(a, c) \
    asm volatile("mbarrier.init.shared.b64 [%0], %1;" :: "r"((uint32_t)(a)), "r"((uint32_t)(c)) : "memory")
#define MB_EXPECT(a, tx) \
    asm volatile("mbarrier.arrive.expect_tx.shared.b64 _, [%0], %1;" :: "r"((uint32_t)(a)), "r"((uint32_t)(tx)) : "memory")
#define MB_WAIT(a, par) do {                                                       \
    uint32_t _m = (uint32_t)(a), _p = (uint32_t)(par), _d;                         \
    asm volatile("{\n\t.reg .pred p;\n\t"                                          \
        "mbarrier.try_wait.parity.shared.b64 p, [%1], %2;\n\t"                     \
        "selp.b32 %0, 1, 0, p;\n\t}" : "=r"(_d) : "r"(_m), "r"(_p) : "memory");    \
    if (!_d) {                                                                     \
        asm volatile("{\n\t.reg .pred P1;\n\t"                                     \
        "WL_%=:\n\t"                                                               \
        "mbarrier.try_wait.parity.shared.b64 P1, [%0], %1;\n\t"                    \
        "@P1 bra.uni WD_%=;\n\t"                                                   \
        "bra.uni WL_%=;\n\t"                                                       \
        "WD_%=:\n\t}" :: "r"(_m), "r"(_p) : "memory");                             \
    } } while (0)
#define FENCE_ASYNC() asm volatile("fence.proxy.async.shared::cta;" ::: "memory")
#define BULK_G2S(dst, src, sz, mbar) \
    asm volatile("cp.async.bulk.shared::cta.global.mbarrier::complete_tx::bytes [%0], [%1], %2, [%3];" \
        :: "r"((uint32_t)(dst)), "l"(__cvta_generic_to_global(src)), "r"((uint32_t)(sz)), "r"((uint32_t)(mbar)) : "memory")

// ---------------- small init kernels ----------------
__global__ void k_zero() {
    int i = blockIdx.x * blockDim.x + threadIdx.x;
    int st = gridDim.x * blockDim.x;
    for (int k = i; k < KW * Bsz * Hh; k += st) g_tmp_h[k] = 0.f;
    for (int k = i; k < Bsz * Hh; k += st) { g_c[k] = 0.f; g_h[k] = 0.f; }
    for (int k = i; k < KW * Bsz; k += st) g_tmp_dis[k] = 0.f;
    if (i < 64) g_needed[i] = 0;
}

__global__ void k_last(const unsigned char* __restrict__ mask) {
    int b = blockIdx.x, v = threadIdx.x;   // blockDim = 64
    __shared__ int nv[64];
    int val = 0;
    if (v < Vn) {
        const unsigned char* mp = mask + ((size_t)b * Vn + v) * Nn;
        int allp = 1;
        for (int n = 0; n < Nn; n++) allp &= (mp[n] != 0);
        val = allp ? 0 : 1;
    }
    nv[v] = val;
    __syncthreads();
    if (v == 0) {
        int c = 0;
        for (int i = 0; i < Vn; i++) c += nv[i];
        int last = c - 1;
        if (last < 0) last += Vn;
        g_last[b] = last;
        g_needed[last] = 1;
    }
}

__global__ void k_wtrans(const float* __restrict__ Wc, const float* __restrict__ Wo) {
    int i = blockIdx.x * blockDim.x + threadIdx.x;
    int st = gridDim.x * blockDim.x;
    for (int idx = i; idx < Hh * Hh * KW; idx += st) {
        int o = idx / (Hh * KW);
        int rem = idx - o * (Hh * KW);
        int h = rem / KW;
        int j = rem - h * KW;
        g_Wct[((size_t)j * Hh + h) * Hh + o] = Wc[idx];
    }
    for (int idx = i; idx < OUTd * Hh; idx += st) {
        int o = idx / Hh, k = idx - o * Hh;
        g_Wot[k * OUTd + o] = Wo[idx];
    }
}

// decode physical element-group position -> (tileRow, logical k-chunk elem)
// e4 = group of 4 fp16 (8 bytes). byte off in tile = (e4*8)&8191.
__device__ __forceinline__ void dec_tile(size_t e4, int& tile, int& row, int& kk) {
    tile = (int)(e4 >> 10);                    // 1024 groups per 8KB tile
    int off = ((int)e4 & 1023) * 8;            // byte offset in tile
    row = off >> 6;
    int w = off & 63;
    int chp = w >> 4;
    int ch = chp ^ ((row >> 1) & 3);
    kk = ch * 8 + ((w & 15) >> 1);             // 0..28, step 4
}

__device__ __forceinline__ uint32_t pkh(__half a, __half b) {
    __half2 t; t.x = a; t.y = b;
    return *(uint32_t*)&t;
}

// convert Wk[:, :8192] to fp16 tiles [ni*256+ck] (GgPad rows, zero pad)
__global__ void k_wkbf(const float* __restrict__ Wk) {
    size_t i = (size_t)blockIdx.x * blockDim.x + threadIdx.x;
    size_t st = (size_t)gridDim.x * blockDim.x;
    const size_t TOT4 = (size_t)GgPad * NDd / 4;
    uint2* ph = (uint2*)g_Wk_h;
    for (size_t e4 = i; e4 < TOT4; e4 += st) {
        int tile, row, kk;
        dec_tile(e4, tile, row, kk);
        int ni = tile >> 8, ck = tile & 255;
        int g = ni * 128 + row;
        int k = ck * 32 + kk;
        float v0 = 0.f, v1 = 0.f, v2 = 0.f, v3 = 0.f;
        if (g < Gg) {
            const float* wr = Wk + (size_t)g * (NDd + 1) + k;
            v0 = wr[0]; v1 = wr[1]; v2 = wr[2]; v3 = wr[3];
        }
        ph[e4] = make_uint2(pkh(__float2half_rn(v0), __float2half_rn(v1)),
                            pkh(__float2half_rn(v2), __float2half_rn(v3)));
    }
}

// gather x = embed[node_ids] -> fp16 tiles [mi*256+ck]; m = v*Bsz+b
// processes tile range [tile0, tile0+ntiles) so chunks can pipeline with the GEMM
__global__ void k_split_rng(const int* __restrict__ ids, const float4* __restrict__ ef4,
                            int tile0, int ntiles) {
    size_t i = (size_t)blockIdx.x * blockDim.x + threadIdx.x;
    size_t st = (size_t)gridDim.x * blockDim.x;
    const size_t base = (size_t)tile0 << 10;
    const size_t CNT4 = (size_t)ntiles << 10;
    uint2* ph = (uint2*)g_A_h;
    for (size_t r = i; r < CNT4; r += st) {
        size_t e4 = base + r;
        int tile, row, kk;
        dec_tile(e4, tile, row, kk);
        int mi = tile >> 8, ck = tile & 255;
        int m = mi * 128 + row;
        int k = ck * 32 + kk;
        int v_ = m >> 8, b = m & 255;
        int id = __ldg(&ids[(b * Vn + v_) * Nn + (k >> 7)]);
        float4 v = __ldg(&ef4[(size_t)id * 32 + ((k & 127) >> 2)]);
        ph[e4] = make_uint2(pkh(__float2half_rn(v.x), __float2half_rn(v.y)),
                            pkh(__float2half_rn(v.z), __float2half_rn(v.w)));
    }
}

// ---------------- tensor-core input projection: bulk-TMA loader + fp16 mma.sync ----------------
// XK[m,g] = sum_d x[m,d]*Wk[g,d] + (bk+br)[g] + vt[m]*(Wk[g,ND]+Wr[g,H])
// single-pass fp16 (error calibrated: ~1.2-1.7e-4, threshold 1e-3).
// smem per stage 16KB: A[8K] W[8K]; NSTG=4 stages = 64KB dynamic; 2 blocks/SM.

__global__ __launch_bounds__(256, 2)
void k_xk_mma(const float* __restrict__ vt, const float* __restrict__ Wk,
              const float* __restrict__ bk, const float* __restrict__ Wr,
              const float* __restrict__ br, int mi0)
{
    extern __shared__ char dsm[];
    __shared__ float bias_s[128], wl_s[128], vt_s[128];
    __shared__ __align__(8) ull mbars[NSTG];
    const uint32_t smb = smem_u32(dsm);
    const int tid = threadIdx.x;
    const int wid = tid >> 5, lane = tid & 31;
    const int wm = wid & 1, wn = wid >> 1;    // warp tile: 64 rows x 32 cols

    const int mi = mi0 + blockIdx.y;          // m-tile (128 v-major rows)
    const int ni = blockIdx.x;
    const int m0 = mi * 128, n0 = ni * 128;

    if (tid < NSTG) MB_INIT(smem_u32(&mbars[tid]), 1);
    if (tid < 128) {
        int g = n0 + tid;
        if (g < Gg) {
            bias_s[tid] = bk[g] + br[g];
            wl_s[tid] = Wk[(size_t)g * (NDd + 1) + NDd] + Wr[(size_t)g * (Hh + 1) + Hh];
        } else { bias_s[tid] = 0.f; wl_s[tid] = 0.f; }
        int m = m0 + tid;
        int v_ = m >> 8, b = m & 255;
        vt_s[tid] = __ldg(&vt[b * Vn + v_]);
    }
    FENCE_ASYNC();
    __syncthreads();

    float acc[4][4][4];
#pragma unroll
    for (int a = 0; a < 4; a++)
#pragma unroll
        for (int b = 0; b < 4; b++)
#pragma unroll
            for (int c = 0; c < 4; c++) acc[a][b][c] = 0.f;

    // prologue: fill NSTG-1 stages
    if (tid == 0) {
#pragma unroll
        for (int s = 0; s < NSTG - 1; s++) {
            uint32_t mb = smem_u32(&mbars[s]);
            uint32_t so = smb + s * STGB;
            size_t at = ((size_t)mi * 256 + s) * 4096;
            size_t bt = ((size_t)ni * 256 + s) * 4096;
            MB_EXPECT(mb, (uint32_t)STGB);
            BULK_G2S(so,        g_A_h  + at, 8192u, mb);
            BULK_G2S(so + 8192, g_Wk_h + bt, 8192u, mb);
        }
    }

    for (int ck = 0; ck < NIT; ck++) {
        const int st = ck & (NSTG - 1);
        MB_WAIT(smem_u32(&mbars[st]), (ck >> 2) & 1);

        uint32_t so = smb + st * STGB;
#pragma unroll
        for (int kc = 0; kc < 2; kc++) {
            uint32_t a_f[4][4], b_f[4][2];
            const int arow = wm * 64 + (lane & 15);
            const int ach = 2 * kc + (lane >> 4);
#pragma unroll
            for (int mt = 0; mt < 4; mt++) {
                int r = arow + mt * 16;
                uint32_t ph = (uint32_t)(r * 64 + ((ach ^ ((r >> 1) & 3)) << 4));
                ldm4(a_f[mt], so + ph);
            }
            const int brow = wn * 32 + ((lane >> 4) & 1) * 8 + (lane & 7);
            const int bch = 2 * kc + ((lane >> 3) & 1);
#pragma unroll
            for (int np = 0; np < 2; np++) {
                int r = brow + np * 16;
                uint32_t ph = (uint32_t)(r * 64 + ((bch ^ ((r >> 1) & 3)) << 4));
                uint32_t t[4];
                ldm4(t, so + 8192 + ph);
                b_f[np * 2][0] = t[0]; b_f[np * 2][1] = t[1];
                b_f[np * 2 + 1][0] = t[2]; b_f[np * 2 + 1][1] = t[3];
            }
#pragma unroll
            for (int mt = 0; mt < 4; mt++)
#pragma unroll
                for (int nt = 0; nt < 4; nt++) mma16816h(acc[mt][nt], a_f[mt], b_f[nt]);
        }
        __syncthreads();   // all threads done reading stage st
        if (tid == 0 && ck + NSTG - 1 < NIT) {
            int nk = ck + NSTG - 1;
            int ns = nk & (NSTG - 1);          // freed by barrier above
            uint32_t mb = smem_u32(&mbars[ns]);
            uint32_t nso = smb + ns * STGB;
            size_t at = ((size_t)mi * 256 + nk) * 4096;
            size_t bt = ((size_t)ni * 256 + nk) * 4096;
            MB_EXPECT(mb, (uint32_t)STGB);
            BULK_G2S(nso,        g_A_h  + at, 8192u, mb);
            BULK_G2S(nso + 8192, g_Wk_h + bt, 8192u, mb);
        }
    }

    // epilogue: fold bias + interval term
#pragma unroll
    for (int mt = 0; mt < 4; mt++) {
        int rl0 = wm * 64 + mt * 16 + (lane >> 2);
        int rl1 = rl0 + 8;
        float v0 = vt_s[rl0], v1 = vt_s[rl1];
        size_t ro0 = (size_t)(m0 + rl0) * Gg;
        size_t ro1 = (size_t)(m0 + rl1) * Gg;
#pragma unroll
        for (int nt = 0; nt < 4; nt++) {
            int gl = wn * 32 + nt * 8 + (lane & 3) * 2;
            int g = n0 + gl;
            if (g < Gg) {
                g_xk[ro0 + g] = acc[mt][nt][0] + bias_s[gl] + v0 * wl_s[gl];
                g_xk[ro1 + g] = acc[mt][nt][2] + bias_s[gl] + v1 * wl_s[gl];
            }
            if (g + 1 < Gg) {
                g_xk[ro0 + g + 1] = acc[mt][nt][1] + bias_s[gl + 1] + v0 * wl_s[gl + 1];
                g_xk[ro1 + g + 1] = acc[mt][nt][3] + bias_s[gl + 1] + v1 * wl_s[gl + 1];
            }
        }
    }
}

// ---------------- recurrent GEMM: xout = XK[t*Bsz+b] + h @ Wr[:, :H].T ----------------
#define RBM 64
#define RBN 64
#define RBK 32

#define RC_LOAD(kc_) {                                                          \
    int kb_ = (kc_) * RBK;                                                      \
    a_s0 = *(const float4*)(&g_h[(b0 + rA0) * Hh + kb_ + (cA0 << 2)]);          \
    a_s1 = *(const float4*)(&g_h[(b0 + rA1) * Hh + kb_ + (cA0 << 2)]);          \
    _Pragma("unroll")                                                           \
    for (int i_ = 0; i_ < 8; i_++) {                                            \
        int e_ = (i_ << 8) + tid; int kl_ = e_ & 31, gl_ = e_ >> 5;             \
        int g_ = g0 + gl_;                                                      \
        b_s[i_] = (g_ < Gg) ? Wr[(size_t)g_ * (Hh + 1) + kb_ + kl_] : 0.f;      \
    } }

#define RC_STORE() {                                                            \
    As[(cA0 << 2) + 0][rA0] = a_s0.x; As[(cA0 << 2) + 1][rA0] = a_s0.y;         \
    As[(cA0 << 2) + 2][rA0] = a_s0.z; As[(cA0 << 2) + 3][rA0] = a_s0.w;         \
    As[(cA0 << 2) + 0][rA1] = a_s1.x; As[(cA0 << 2) + 1][rA1] = a_s1.y;         \
    As[(cA0 << 2) + 2][rA1] = a_s1.z; As[(cA0 << 2) + 3][rA1] = a_s1.w;         \
    _Pragma("unroll")                                                           \
    for (int i_ = 0; i_ < 8; i_++) {                                            \
        int e_ = (i_ << 8) + tid; Bs[e_ & 31][e_ >> 5] = b_s[i_];               \
    } }

#define RC_COMPUTE() {                                                          \
    _Pragma("unroll")                                                           \
    for (int kk = 0; kk < RBK; kk++) {                                          \
        float4 av_ = *(const float4*)(&As[kk][ty << 2]);                        \
        float4 bv_ = *(const float4*)(&Bs[kk][tx << 2]);                        \
        float aa_[4] = {av_.x, av_.y, av_.z, av_.w};                            \
        float bb_[4] = {bv_.x, bv_.y, bv_.z, bv_.w};                            \
        _Pragma("unroll")                                                       \
        for (int i_ = 0; i_ < 4; i_++)                                          \
            _Pragma("unroll")                                                   \
            for (int j_ = 0; j_ < 4; j_++)                                      \
                acc[i_][j_] += aa_[i_] * bb_[j_];                               \
    } }

__global__ __launch_bounds__(256) void k_rec(const float* __restrict__ Wr, int t)
{
    __shared__ float As[RBK][RBM];
    __shared__ float Bs[RBK][RBN];
    const int tid = threadIdx.x;
    const int tx = tid & 15, ty = tid >> 4;
    const int g0 = blockIdx.x * RBN;
    const int b0 = blockIdx.y * RBM;
    const int rA0 = tid >> 3, cA0 = tid & 7, rA1 = rA0 + 32;

    float acc[4][4] = {};
    float4 a_s0, a_s1;
    float b_s[8];

    RC_LOAD(0);
    RC_STORE();
    __syncthreads();
    for (int kc = 1; kc < Hh / RBK; kc++) {
        RC_LOAD(kc);
        RC_COMPUTE();
        __syncthreads();
        RC_STORE();
        __syncthreads();
    }
    RC_COMPUTE();

#pragma unroll
    for (int i = 0; i < 4; i++) {
        int b = b0 + (ty << 2) + i;
#pragma unroll
        for (int j = 0; j < 4; j++) {
            int g = g0 + (tx << 2) + j;
            if (g < Gg)
                g_xout[b * Gg + g] = acc[i][j] + g_xk[((size_t)t * Bsz + b) * Gg + g];
        }
    }
}

// ---------------- LSTM cell + ring + local_dis + theme ----------------
__global__ __launch_bounds__(128) void k_cell(
    const float* __restrict__ Ws, const float* __restrict__ bs,
    const float* __restrict__ Wrs, const float* __restrict__ brs, int t)
{
    const int b = blockIdx.x, tid = threadIdx.x;
    __shared__ float z16[16];
    __shared__ float fm[Ll], im[Ll];
    __shared__ float thm[Hh];
    __shared__ float s64[64];
    __shared__ float ldl[KW];

    if (tid < 16) z16[tid] = g_xout[b * Gg + tid];
    __syncthreads();

    const int slot = t % KW;
    if (tid == 0) {
        float m = -1e30f;
        for (int i = 0; i < Ll; i++) m = fmaxf(m, z16[i]);
        float s[Ll], tot = 0.f;
        for (int i = 0; i < Ll; i++) { s[i] = expf(z16[i] - m); tot += s[i]; }
        float inv = 1.f / tot, cum = 0.f, msum = 0.f;
        for (int i = 0; i < Ll; i++) { cum += s[i] * inv; fm[i] = cum; msum += cum; }
        g_tmp_dis[slot * Bsz + b] = 1.f - msum * (1.f / Ll);
    }
    if (tid == 1) {
        float m = -1e30f;
        for (int i = 0; i < Ll; i++) m = fmaxf(m, z16[8 + i]);
        float s[Ll], tot = 0.f;
        for (int i = 0; i < Ll; i++) { s[i] = expf(z16[8 + i] - m); tot += s[i]; }
        float inv = 1.f / tot, cum = 0.f;
        for (int i = Ll - 1; i >= 0; i--) { cum += s[i] * inv; im[i] = cum; }
    }
    __syncthreads();

    const float* xo = &g_xout[b * Gg + 16];
    for (int e = tid; e < Hh; e += 128) {
        int l = e / CHc, j = e - l * CHc;
        float fg = sigf(xo[l * CHc + j]);
        float ig = sigf(xo[(Ll + l) * CHc + j]);
        float og = sigf(xo[(2 * Ll + l) * CHc + j]);
        float ci = tanhf(xo[(3 * Ll + l) * CHc + j]);
        float cl = g_c[b * Hh + e];
        float fmv = fm[l], imv = im[l], ovv = fmv * imv;
        float cn = ovv * (fg * cl + ig * ci) + (fmv - ovv) * cl + (imv - ovv) * ci;
        float hn = og * tanhf(cn);
        g_c[b * Hh + e] = cn;
        g_h[b * Hh + e] = hn;
        g_tmp_h[(slot * Bsz + b) * Hh + e] = hn;
    }

    if (!g_needed[t]) return;
    __syncthreads();

    if (tid == 0) {
        float d[KW], c = 0.f;
        for (int k = 0; k < KW; k++) {
            int sk = (t + 1 + k) % KW;
            c += g_tmp_dis[sk * Bsz + b];
            d[k] = c;
        }
        float m = -1e30f;
        for (int k = 0; k < KW; k++) m = fmaxf(m, d[k]);
        float tot = 0.f;
        for (int k = 0; k < KW; k++) { d[k] = expf(d[k] - m); tot += d[k]; }
        float inv = 1.f / tot;
        for (int k = 0; k < KW; k++) {
            ldl[k] = d[k] * inv;
            g_ld[b * KW + k] = ldl[k];
        }
    }
    __syncthreads();

    for (int e = tid; e < Hh; e += 128) {
        float s = 0.f;
        for (int k = 0; k < KW; k++) {
            int sk = (t + 1 + k) % KW;
            s += ldl[k] * g_tmp_h[(sk * Bsz + b) * Hh + e];
        }
        thm[e] = s * (1.f / KW);
    }
    __syncthreads();

    if (tid < 64) {
        float a = bs[tid];
        const float* w = &Ws[tid * Hh];
        for (int kk = 0; kk < Hh; kk++) a += thm[kk] * w[kk];
        s64[tid] = fmaxf(a, 0.f);
    }
    __syncthreads();

    for (int e = tid; e < Hh; e += 128) {
        float a = brs[e];
        const float* w = &Wrs[e * 64];
#pragma unroll
        for (int kk = 0; kk < 64; kk++) a += s64[kk] * w[kk];
        g_theme[b * Hh + e] = sigf(a);
    }
}

// ---------------- conv partials (only at needed steps) ----------------
#define CV_LOAD(kc_) {                                                          \
    int kb_ = (kc_) * RBK;                                                      \
    a_s0 = *(const float4*)(&A[(b0 + rA0) * Hh + kb_ + (cA0 << 2)]);            \
    a_s1 = *(const float4*)(&A[(b0 + rA1) * Hh + kb_ + (cA0 << 2)]);            \
    b_s0 = *(const float4*)(&Bm[(size_t)(kb_ + rB0) * Hh + o0 + (cB0 << 2)]);   \
    b_s1 = *(const float4*)(&Bm[(size_t)(kb_ + rB1) * Hh + o0 + (cB0 << 2)]);   \
    }

#define CV_STORE() {                                                            \
    As[(cA0 << 2) + 0][rA0] = a_s0.x; As[(cA0 << 2) + 1][rA0] = a_s0.y;         \
    As[(cA0 << 2) + 2][rA0] = a_s0.z; As[(cA0 << 2) + 3][rA0] = a_s0.w;         \
    As[(cA0 << 2) + 0][rA1] = a_s1.x; As[(cA0 << 2) + 1][rA1] = a_s1.y;         \
    As[(cA0 << 2) + 2][rA1] = a_s1.z; As[(cA0 << 2) + 3][rA1] = a_s1.w;         \
    *(float4*)(&Bs[rB0][cB0 << 2]) = b_s0;                                      \
    *(float4*)(&Bs[rB1][cB0 << 2]) = b_s1;                                      \
    }

__global__ __launch_bounds__(256) void k_conv(int t)
{
    if (!g_needed[t]) return;
    __shared__ float As[RBK][RBM];
    __shared__ float Bs[RBK][RBN];
    const int tid = threadIdx.x;
    const int tx = tid & 15, ty = tid >> 4;
    const int o0 = blockIdx.x * RBN;
    const int b0 = blockIdx.y * RBM;
    const int j = blockIdx.z;
    const int slot = (t + 1 + j) % KW;
    const float* A = g_tmp_h + (size_t)slot * Bsz * Hh;
    const float* Bm = g_Wct + (size_t)j * Hh * Hh;
    const int rA0 = tid >> 3, cA0 = tid & 7, rA1 = rA0 + 32;
    const int rB0 = tid >> 4, cB0 = tid & 15, rB1 = rB0 + 16;

    float acc[4][4] = {};
    float4 a_s0, a_s1, b_s0, b_s1;

    CV_LOAD(0);
    CV_STORE();
    __syncthreads();
    for (int kc = 1; kc < Hh / RBK; kc++) {
        CV_LOAD(kc);
        RC_COMPUTE();
        __syncthreads();
        CV_STORE();
        __syncthreads();
    }
    RC_COMPUTE();

#pragma unroll
    for (int i = 0; i < 4; i++) {
        int b = b0 + (ty << 2) + i;
#pragma unroll
        for (int jj = 0; jj < 4; jj++) {
            int o = o0 + (tx << 2) + jj;
            g_conv_part[((size_t)j * Bsz + b) * Hh + o] = acc[i][jj];
        }
    }
}

__global__ void k_reduce(const float* __restrict__ bc, int t)
{
    if (!g_needed[t]) return;
    int b = blockIdx.x, e = threadIdx.x;   // blockDim = 384
    float a = bc[e];
#pragma unroll
    for (int j = 0; j < KW; j++)
        a += g_ld[b * KW + j] * g_conv_part[((size_t)j * Bsz + b) * Hh + e];
    float r = g_h[b * Hh + e] + g_theme[b * Hh + e] * a;
    if (g_last[b] == t) g_rnn_last[b * Hh + e] = r;
}

// ---------------- final output GEMV ----------------
__global__ __launch_bounds__(128) void k_out(const float* __restrict__ bo, float* __restrict__ out)
{
    int b = blockIdx.x, o = threadIdx.x;
    __shared__ float r[Hh];
    for (int e = o; e < Hh; e += 128) r[e] = g_rnn_last[b * Hh + e];
    __syncthreads();
    float a = bo[o];
    for (int k = 0; k < Hh; k++) a += r[k] * g_Wot[k * OUTd + o];
    out[b * OUTd + o] = a;
}

// ---------------- launch: split chunks -> GEMM chunks -> scan chunks, all pipelined ----------------
#define NCHUNKS 3
static const int c_vlo[NCHUNKS] = {0, 22, 44};
static const int c_vhi[NCHUNKS] = {22, 44, 50};

extern "C" void kernel_launch(void* const* d_in, const int* in_sizes, int n_in,
                              void* d_out, int out_size)
{
    const int*           node_ids    = (const int*)d_in[0];
    const float*         visit_times = (const float*)d_in[3];
    const unsigned char* attn_mask   = (const unsigned char*)d_in[5];
    const float*         embed       = (const float*)d_in[6];
    const float*         Wk          = (const float*)d_in[7];
    const float*         bk          = (const float*)d_in[8];
    const float*         Wr          = (const float*)d_in[9];
    const float*         br          = (const float*)d_in[10];
    const float*         Ws          = (const float*)d_in[11];
    const float*         bs          = (const float*)d_in[12];
    const float*         Wrs         = (const float*)d_in[13];
    const float*         brs         = (const float*)d_in[14];
    const float*         Wc          = (const float*)d_in[15];
    const float*         bc          = (const float*)d_in[16];
    const float*         Wo          = (const float*)d_in[17];
    const float*         bo          = (const float*)d_in[18];
    float*               out         = (float*)d_out;

    static int inited = 0;
    static cudaStream_t s2, s3;
    static cudaEvent_t evFork, evJoin, evC[NCHUNKS], evS[NCHUNKS];
    if (!inited) {
        cudaFuncSetAttribute(k_xk_mma, cudaFuncAttributeMaxDynamicSharedMemorySize, NSTG * STGB);
        cudaStreamCreateWithFlags(&s2, cudaStreamNonBlocking);
        cudaStreamCreateWithFlags(&s3, cudaStreamNonBlocking);
        cudaEventCreateWithFlags(&evFork, cudaEventDisableTiming);
        cudaEventCreateWithFlags(&evJoin, cudaEventDisableTiming);
        for (int c = 0; c < NCHUNKS; c++) {
            cudaEventCreateWithFlags(&evC[c], cudaEventDisableTiming);
            cudaEventCreateWithFlags(&evS[c], cudaEventDisableTiming);
        }
        inited = 1;
    }

    // ---- prep on primary stream (small kernels + W convert) ----
    k_zero<<<512, 256>>>();
    k_last<<<Bsz, 64>>>(attn_mask);
    k_wtrans<<<512, 256>>>(Wc, Wo);
    k_wkbf<<<2048, 256>>>(Wk);

    // fork s2 (scan) and s3 (A split) from primary
    cudaEventRecord(evFork, 0);
    cudaStreamWaitEvent(s2, evFork, 0);
    cudaStreamWaitEvent(s3, evFork, 0);

    // ---- A-split chunks on s3; GEMM chunk c waits on split chunk c ----
    for (int c = 0; c < NCHUNKS; c++) {
        int t0 = c_vlo[c] * 2 * 256;                    // mi0 * 256 tiles
        int nt = (c_vhi[c] - c_vlo[c]) * 2 * 256;
        k_split_rng<<<4096, 256, 0, s3>>>(node_ids, (const float4*)embed, t0, nt);
        cudaEventRecord(evS[c], s3);
    }

    // ---- GEMM chunks on primary; gated on their split chunk; event after each ----
    for (int c = 0; c < NCHUNKS; c++) {
        cudaStreamWaitEvent(0, evS[c], 0);
        int mi0 = c_vlo[c] * 2;
        int nmt = (c_vhi[c] - c_vlo[c]) * 2;
        dim3 gx(13, nmt);
        k_xk_mma<<<gx, 256, NSTG * STGB, 0>>>(visit_times, Wk, bk, Wr, br, mi0);
        cudaEventRecord(evC[c], 0);
    }

    // ---- scan chunks on s2, each gated on its GEMM chunk ----
    for (int c = 0; c < NCHUNKS; c++) {
        cudaStreamWaitEvent(s2, evC[c], 0);
        for (int t = c_vlo[c]; t < c_vhi[c]; t++) {
            dim3 gr(25, 4);
            k_rec<<<gr, 256, 0, s2>>>(Wr, t);
            k_cell<<<Bsz, 128, 0, s2>>>(Ws, bs, Wrs, brs, t);
            dim3 gc(6, 4, KW);
            k_conv<<<gc, 256, 0, s2>>>(t);
            k_reduce<<<Bsz, Hh, 0, s2>>>(bc, t);
        }
    }
    k_out<<<Bsz, 128, 0, s2>>>(bo, out);

    // join back to primary stream
    cudaEventRecord(evJoin, s2);
    cudaStreamWaitEvent(0, evJoin, 0);
}

// round 15
// speedup vs baseline: 1.4572x; 1.0003x over previous
#include <cuda_runtime.h>
#include <cuda_fp16.h>
#include <math.h>
#include <stdint.h>

#define Bsz 256
#define Vn  50
#define Nn  64
#define Dd  128
#define NDd 8192
#define Hh  384
#define Ll  8
#define CHc 48
#define KW  10
#define OUTd 128
#define Gg  1552
#define GgPad 1664
#define Mtot 12800          /* B*V ; m = v*Bsz + b (v-major) */
#define NIT 256             /* 8192 / 32 */
#define NSTG 4              /* pipeline stages, 16KB each */
#define STGB 16384
#define KCV (KW * Hh)       /* 3840: conv contraction dim */

typedef unsigned long long ull;

// ---------------- device scratch (no allocs allowed) ----------------
__device__ float g_xk[(size_t)Mtot * Gg];          // [v*Bsz+b][g]
__device__ float g_xout[Bsz * Gg];
__device__ float g_h[Bsz * Hh];
__device__ float g_c[Bsz * Hh];
__device__ float g_tmp_h[KW * Bsz * Hh];
__device__ float g_tmp_dis[KW * Bsz];
__device__ float g_theme[Bsz * Hh];
__device__ float g_localh[Bsz * KCV];              // snapshot: ld[k]*tmp_h at b's last step
__device__ float g_hsnap[Bsz * Hh];                // snapshot: h at b's last step
__device__ float g_convout[Bsz * Hh];
__device__ float g_Wct[KW * Hh * Hh];              // [(j*Hh+h)][o]  (K-major for conv GEMM)
__device__ float g_Wot[Hh * OUTd];
__device__ int   g_last[Bsz];
__device__ int   g_needed[64];
// pre-tiled, pre-swizzled 8KB tiles: [tileIdx*256 + ck] * 4096 fp16 elems
__device__ __align__(256) __half g_Wk_h[(size_t)GgPad * NDd];
__device__ __align__(256) __half g_A_h[(size_t)Mtot * NDd];

__device__ __forceinline__ float sigf(float x) { return 1.0f / (1.0f + expf(-x)); }

__device__ __forceinline__ uint32_t smem_u32(const void* p) {
    uint32_t a;
    asm("{ .reg .u64 t; cvta.to.shared.u64 t, %1; cvt.u32.u64 %0, t; }" : "=r"(a) : "l"(p));
    return a;
}

// ---------------- sm_90-era async + sm_80 tensor path (valid under .target sm_103) ----------------
__device__ __forceinline__ void ldm4(uint32_t* r, uint32_t addr) {
    asm volatile("ldmatrix.sync.aligned.m8n8.x4.shared.b16 {%0,%1,%2,%3}, [%4];"
                 : "=r"(r[0]), "=r"(r[1]), "=r"(r[2]), "=r"(r[3]) : "r"(addr));
}
__device__ __forceinline__ void mma16816h(float* c, const uint32_t* a, const uint32_t* b) {
    asm volatile("mma.sync.aligned.m16n8k16.row.col.f32.f16.f16.f32 "
                 "{%0,%1,%2,%3}, {%4,%5,%6,%7}, {%8,%9}, {%0,%1,%2,%3};"
                 : "+f"(c[0]), "+f"(c[1]), "+f"(c[2]), "+f"(c[3])
                 : "r"(a[0]), "r"(a[1]), "r"(a[2]), "r"(a[3]), "r"(b[0]), "r"(b[1]));
}

#define MB_INIT(a, c) \
    asm volatile("mbarrier.init.shared.b64 [%0], %1;" :: "r"((uint32_t)(a)), "r"((uint32_t)(c)) : "memory")
#define MB_EXPECT(a, tx) \
    asm volatile("mbarrier.arrive.expect_tx.shared.b64 _, [%0], %1;" :: "r"((uint32_t)(a)), "r"((uint32_t)(tx)) : "memory")
#define MB_WAIT(a, par) do {                                                       \
    uint32_t _m = (uint32_t)(a), _p = (uint32_t)(par), _d;                         \
    asm volatile("{\n\t.reg .pred p;\n\t"                                          \
        "mbarrier.try_wait.parity.shared.b64 p, [%1], %2;\n\t"                     \
        "selp.b32 %0, 1, 0, p;\n\t}" : "=r"(_d) : "r"(_m), "r"(_p) : "memory");    \
    if (!_d) {                                                                     \
        asm volatile("{\n\t.reg .pred P1;\n\t"                                     \
        "WL_%=:\n\t"                                                               \
        "mbarrier.try_wait.parity.shared.b64 P1, [%0], %1;\n\t"                    \
        "@P1 bra.uni WD_%=;\n\t"                                                   \
        "bra.uni WL_%=;\n\t"                                                       \
        "WD_%=:\n\t}" :: "r"(_m), "r"(_p) : "memory");                             \
    } } while (0)
#define FENCE_ASYNC() asm volatile("fence.proxy.async.shared::cta;" ::: "memory")
#define BULK_G2S(dst, src, sz, mbar) \
    asm volatile("cp.async.bulk.shared::cta.global.mbarrier::complete_tx::bytes [%0], [%1], %2, [%3];" \
        :: "r"((uint32_t)(dst)), "l"(__cvta_generic_to_global(src)), "r"((uint32_t)(sz)), "r"((uint32_t)(mbar)) : "memory")

// ---------------- small init kernels ----------------
__global__ void k_zero() {
    int i = blockIdx.x * blockDim.x + threadIdx.x;
    int st = gridDim.x * blockDim.x;
    for (int k = i; k < KW * Bsz * Hh; k += st) g_tmp_h[k] = 0.f;
    for (int k = i; k < Bsz * Hh; k += st) { g_c[k] = 0.f; g_h[k] = 0.f; }
    for (int k = i; k < KW * Bsz; k += st) g_tmp_dis[k] = 0.f;
    if (i < 64) g_needed[i] = 0;
}

__global__ void k_last(const unsigned char* __restrict__ mask) {
    int b = blockIdx.x, v = threadIdx.x;   // blockDim = 64
    __shared__ int nv[64];
    int val = 0;
    if (v < Vn) {
        const unsigned char* mp = mask + ((size_t)b * Vn + v) * Nn;
        int allp = 1;
        for (int n = 0; n < Nn; n++) allp &= (mp[n] != 0);
        val = allp ? 0 : 1;
    }
    nv[v] = val;
    __syncthreads();
    if (v == 0) {
        int c = 0;
        for (int i = 0; i < Vn; i++) c += nv[i];
        int last = c - 1;
        if (last < 0) last += Vn;
        g_last[b] = last;
        g_needed[last] = 1;
    }
}

__global__ void k_wtrans(const float* __restrict__ Wc, const float* __restrict__ Wo) {
    int i = blockIdx.x * blockDim.x + threadIdx.x;
    int st = gridDim.x * blockDim.x;
    for (int idx = i; idx < Hh * Hh * KW; idx += st) {
        int o = idx / (Hh * KW);
        int rem = idx - o * (Hh * KW);
        int h = rem / KW;
        int j = rem - h * KW;
        g_Wct[((size_t)j * Hh + h) * Hh + o] = Wc[idx];
    }
    for (int idx = i; idx < OUTd * Hh; idx += st) {
        int o = idx / Hh, k = idx - o * Hh;
        g_Wot[k * OUTd + o] = Wo[idx];
    }
}

// decode physical element-group position -> (tileRow, logical k-chunk elem)
__device__ __forceinline__ void dec_tile(size_t e4, int& tile, int& row, int& kk) {
    tile = (int)(e4 >> 10);                    // 1024 groups per 8KB tile
    int off = ((int)e4 & 1023) * 8;            // byte offset in tile
    row = off >> 6;
    int w = off & 63;
    int chp = w >> 4;
    int ch = chp ^ ((row >> 1) & 3);
    kk = ch * 8 + ((w & 15) >> 1);             // 0..28, step 4
}

__device__ __forceinline__ uint32_t pkh(__half a, __half b) {
    __half2 t; t.x = a; t.y = b;
    return *(uint32_t*)&t;
}

// convert Wk[:, :8192] to fp16 tiles [ni*256+ck] (GgPad rows, zero pad)
__global__ void k_wkbf(const float* __restrict__ Wk) {
    size_t i = (size_t)blockIdx.x * blockDim.x + threadIdx.x;
    size_t st = (size_t)gridDim.x * blockDim.x;
    const size_t TOT4 = (size_t)GgPad * NDd / 4;
    uint2* ph = (uint2*)g_Wk_h;
    for (size_t e4 = i; e4 < TOT4; e4 += st) {
        int tile, row, kk;
        dec_tile(e4, tile, row, kk);
        int ni = tile >> 8, ck = tile & 255;
        int g = ni * 128 + row;
        int k = ck * 32 + kk;
        float v0 = 0.f, v1 = 0.f, v2 = 0.f, v3 = 0.f;
        if (g < Gg) {
            const float* wr = Wk + (size_t)g * (NDd + 1) + k;
            v0 = wr[0]; v1 = wr[1]; v2 = wr[2]; v3 = wr[3];
        }
        ph[e4] = make_uint2(pkh(__float2half_rn(v0), __float2half_rn(v1)),
                            pkh(__float2half_rn(v2), __float2half_rn(v3)));
    }
}

// gather x = embed[node_ids] -> fp16 tiles [mi*256+ck]; m = v*Bsz+b
__global__ void k_split_rng(const int* __restrict__ ids, const float4* __restrict__ ef4,
                            int tile0, int ntiles) {
    size_t i = (size_t)blockIdx.x * blockDim.x + threadIdx.x;
    size_t st = (size_t)gridDim.x * blockDim.x;
    const size_t base = (size_t)tile0 << 10;
    const size_t CNT4 = (size_t)ntiles << 10;
    uint2* ph = (uint2*)g_A_h;
    for (size_t r = i; r < CNT4; r += st) {
        size_t e4 = base + r;
        int tile, row, kk;
        dec_tile(e4, tile, row, kk);
        int mi = tile >> 8, ck = tile & 255;
        int m = mi * 128 + row;
        int k = ck * 32 + kk;
        int v_ = m >> 8, b = m & 255;
        int id = __ldg(&ids[(b * Vn + v_) * Nn + (k >> 7)]);
        float4 v = __ldg(&ef4[(size_t)id * 32 + ((k & 127) >> 2)]);
        ph[e4] = make_uint2(pkh(__float2half_rn(v.x), __float2half_rn(v.y)),
                            pkh(__float2half_rn(v.z), __float2half_rn(v.w)));
    }
}

// ---------------- tensor-core input projection: bulk-TMA loader + fp16 mma.sync ----------------
__global__ __launch_bounds__(256, 2)
void k_xk_mma(const float* __restrict__ vt, const float* __restrict__ Wk,
              const float* __restrict__ bk, const float* __restrict__ Wr,
              const float* __restrict__ br, int mi0)
{
    extern __shared__ char dsm[];
    __shared__ float bias_s[128], wl_s[128], vt_s[128];
    __shared__ __align__(8) ull mbars[NSTG];
    const uint32_t smb = smem_u32(dsm);
    const int tid = threadIdx.x;
    const int wid = tid >> 5, lane = tid & 31;
    const int wm = wid & 1, wn = wid >> 1;    // warp tile: 64 rows x 32 cols

    const int mi = mi0 + blockIdx.y;
    const int ni = blockIdx.x;
    const int m0 = mi * 128, n0 = ni * 128;

    if (tid < NSTG) MB_INIT(smem_u32(&mbars[tid]), 1);
    if (tid < 128) {
        int g = n0 + tid;
        if (g < Gg) {
            bias_s[tid] = bk[g] + br[g];
            wl_s[tid] = Wk[(size_t)g * (NDd + 1) + NDd] + Wr[(size_t)g * (Hh + 1) + Hh];
        } else { bias_s[tid] = 0.f; wl_s[tid] = 0.f; }
        int m = m0 + tid;
        int v_ = m >> 8, b = m & 255;
        vt_s[tid] = __ldg(&vt[b * Vn + v_]);
    }
    FENCE_ASYNC();
    __syncthreads();

    float acc[4][4][4];
#pragma unroll
    for (int a = 0; a < 4; a++)
#pragma unroll
        for (int b = 0; b < 4; b++)
#pragma unroll
            for (int c = 0; c < 4; c++) acc[a][b][c] = 0.f;

    if (tid == 0) {
#pragma unroll
        for (int s = 0; s < NSTG - 1; s++) {
            uint32_t mb = smem_u32(&mbars[s]);
            uint32_t so = smb + s * STGB;
            size_t at = ((size_t)mi * 256 + s) * 4096;
            size_t bt = ((size_t)ni * 256 + s) * 4096;
            MB_EXPECT(mb, (uint32_t)STGB);
            BULK_G2S(so,        g_A_h  + at, 8192u, mb);
            BULK_G2S(so + 8192, g_Wk_h + bt, 8192u, mb);
        }
    }

    for (int ck = 0; ck < NIT; ck++) {
        const int st = ck & (NSTG - 1);
        MB_WAIT(smem_u32(&mbars[st]), (ck >> 2) & 1);

        uint32_t so = smb + st * STGB;
#pragma unroll
        for (int kc = 0; kc < 2; kc++) {
            uint32_t a_f[4][4], b_f[4][2];
            const int arow = wm * 64 + (lane & 15);
            const int ach = 2 * kc + (lane >> 4);
#pragma unroll
            for (int mt = 0; mt < 4; mt++) {
                int r = arow + mt * 16;
                uint32_t ph = (uint32_t)(r * 64 + ((ach ^ ((r >> 1) & 3)) << 4));
                ldm4(a_f[mt], so + ph);
            }
            const int brow = wn * 32 + ((lane >> 4) & 1) * 8 + (lane & 7);
            const int bch = 2 * kc + ((lane >> 3) & 1);
#pragma unroll
            for (int np = 0; np < 2; np++) {
                int r = brow + np * 16;
                uint32_t ph = (uint32_t)(r * 64 + ((bch ^ ((r >> 1) & 3)) << 4));
                uint32_t t[4];
                ldm4(t, so + 8192 + ph);
                b_f[np * 2][0] = t[0]; b_f[np * 2][1] = t[1];
                b_f[np * 2 + 1][0] = t[2]; b_f[np * 2 + 1][1] = t[3];
            }
#pragma unroll
            for (int mt = 0; mt < 4; mt++)
#pragma unroll
                for (int nt = 0; nt < 4; nt++) mma16816h(acc[mt][nt], a_f[mt], b_f[nt]);
        }
        __syncthreads();
        if (tid == 0 && ck + NSTG - 1 < NIT) {
            int nk = ck + NSTG - 1;
            int ns = nk & (NSTG - 1);
            uint32_t mb = smem_u32(&mbars[ns]);
            uint32_t nso = smb + ns * STGB;
            size_t at = ((size_t)mi * 256 + nk) * 4096;
            size_t bt = ((size_t)ni * 256 + nk) * 4096;
            MB_EXPECT(mb, (uint32_t)STGB);
            BULK_G2S(nso,        g_A_h  + at, 8192u, mb);
            BULK_G2S(nso + 8192, g_Wk_h + bt, 8192u, mb);
        }
    }

#pragma unroll
    for (int mt = 0; mt < 4; mt++) {
        int rl0 = wm * 64 + mt * 16 + (lane >> 2);
        int rl1 = rl0 + 8;
        float v0 = vt_s[rl0], v1 = vt_s[rl1];
        size_t ro0 = (size_t)(m0 + rl0) * Gg;
        size_t ro1 = (size_t)(m0 + rl1) * Gg;
#pragma unroll
        for (int nt = 0; nt < 4; nt++) {
            int gl = wn * 32 + nt * 8 + (lane & 3) * 2;
            int g = n0 + gl;
            if (g < Gg) {
                g_xk[ro0 + g] = acc[mt][nt][0] + bias_s[gl] + v0 * wl_s[gl];
                g_xk[ro1 + g] = acc[mt][nt][2] + bias_s[gl] + v1 * wl_s[gl];
            }
            if (g + 1 < Gg) {
                g_xk[ro0 + g + 1] = acc[mt][nt][1] + bias_s[gl + 1] + v0 * wl_s[gl + 1];
                g_xk[ro1 + g + 1] = acc[mt][nt][3] + bias_s[gl + 1] + v1 * wl_s[gl + 1];
            }
        }
    }
}

// ---------------- recurrent GEMM: xout = XK[t*Bsz+b] + h @ Wr[:, :H].T ----------------
#define RBM 64
#define RBN 64
#define RBK 32

#define RC_LOAD(kc_) {                                                          \
    int kb_ = (kc_) * RBK;                                                      \
    a_s0 = *(const float4*)(&g_h[(b0 + rA0) * Hh + kb_ + (cA0 << 2)]);          \
    a_s1 = *(const float4*)(&g_h[(b0 + rA1) * Hh + kb_ + (cA0 << 2)]);          \
    _Pragma("unroll")                                                           \
    for (int i_ = 0; i_ < 8; i_++) {                                            \
        int e_ = (i_ << 8) + tid; int kl_ = e_ & 31, gl_ = e_ >> 5;             \
        int g_ = g0 + gl_;                                                      \
        b_s[i_] = (g_ < Gg) ? Wr[(size_t)g_ * (Hh + 1) + kb_ + kl_] : 0.f;      \
    } }

#define RC_STORE() {                                                            \
    As[(cA0 << 2) + 0][rA0] = a_s0.x; As[(cA0 << 2) + 1][rA0] = a_s0.y;         \
    As[(cA0 << 2) + 2][rA0] = a_s0.z; As[(cA0 << 2) + 3][rA0] = a_s0.w;         \
    As[(cA0 << 2) + 0][rA1] = a_s1.x; As[(cA0 << 2) + 1][rA1] = a_s1.y;         \
    As[(cA0 << 2) + 2][rA1] = a_s1.z; As[(cA0 << 2) + 3][rA1] = a_s1.w;         \
    _Pragma("unroll")                                                           \
    for (int i_ = 0; i_ < 8; i_++) {                                            \
        int e_ = (i_ << 8) + tid; Bs[e_ & 31][e_ >> 5] = b_s[i_];               \
    } }

#define RC_COMPUTE() {                                                          \
    _Pragma("unroll")                                                           \
    for (int kk = 0; kk < RBK; kk++) {                                          \
        float4 av_ = *(const float4*)(&As[kk][ty << 2]);                        \
        float4 bv_ = *(const float4*)(&Bs[kk][tx << 2]);                        \
        float aa_[4] = {av_.x, av_.y, av_.z, av_.w};                            \
        float bb_[4] = {bv_.x, bv_.y, bv_.z, bv_.w};                            \
        _Pragma("unroll")                                                       \
        for (int i_ = 0; i_ < 4; i_++)                                          \
            _Pragma("unroll")                                                   \
            for (int j_ = 0; j_ < 4; j_++)                                      \
                acc[i_][j_] += aa_[i_] * bb_[j_];                               \
    } }

__global__ __launch_bounds__(256) void k_rec(const float* __restrict__ Wr, int t)
{
    __shared__ float As[RBK][RBM];
    __shared__ float Bs[RBK][RBN];
    const int tid = threadIdx.x;
    const int tx = tid & 15, ty = tid >> 4;
    const int g0 = blockIdx.x * RBN;
    const int b0 = blockIdx.y * RBM;
    const int rA0 = tid >> 3, cA0 = tid & 7, rA1 = rA0 + 32;

    float acc[4][4] = {};
    float4 a_s0, a_s1;
    float b_s[8];

    RC_LOAD(0);
    RC_STORE();
    __syncthreads();
    for (int kc = 1; kc < Hh / RBK; kc++) {
        RC_LOAD(kc);
        RC_COMPUTE();
        __syncthreads();
        RC_STORE();
        __syncthreads();
    }
    RC_COMPUTE();

#pragma unroll
    for (int i = 0; i < 4; i++) {
        int b = b0 + (ty << 2) + i;
#pragma unroll
        for (int j = 0; j < 4; j++) {
            int g = g0 + (tx << 2) + j;
            if (g < Gg)
                g_xout[b * Gg + g] = acc[i][j] + g_xk[((size_t)t * Bsz + b) * Gg + g];
        }
    }
}

// ---------------- LSTM cell + ring + local_dis + theme + snapshots ----------------
__global__ __launch_bounds__(128) void k_cell(
    const float* __restrict__ Ws, const float* __restrict__ bs,
    const float* __restrict__ Wrs, const float* __restrict__ brs, int t)
{
    const int b = blockIdx.x, tid = threadIdx.x;
    __shared__ float z16[16];
    __shared__ float fm[Ll], im[Ll];
    __shared__ float thm[Hh];
    __shared__ float s64[64];
    __shared__ float ldl[KW];

    if (tid < 16) z16[tid] = g_xout[b * Gg + tid];
    __syncthreads();

    const int slot = t % KW;
    const int mine = (g_last[b] == t);
    if (tid == 0) {
        float m = -1e30f;
        for (int i = 0; i < Ll; i++) m = fmaxf(m, z16[i]);
        float s[Ll], tot = 0.f;
        for (int i = 0; i < Ll; i++) { s[i] = expf(z16[i] - m); tot += s[i]; }
        float inv = 1.f / tot, cum = 0.f, msum = 0.f;
        for (int i = 0; i < Ll; i++) { cum += s[i] * inv; fm[i] = cum; msum += cum; }
        g_tmp_dis[slot * Bsz + b] = 1.f - msum * (1.f / Ll);
    }
    if (tid == 1) {
        float m = -1e30f;
        for (int i = 0; i < Ll; i++) m = fmaxf(m, z16[8 + i]);
        float s[Ll], tot = 0.f;
        for (int i = 0; i < Ll; i++) { s[i] = expf(z16[8 + i] - m); tot += s[i]; }
        float inv = 1.f / tot, cum = 0.f;
        for (int i = Ll - 1; i >= 0; i--) { cum += s[i] * inv; im[i] = cum; }
    }
    __syncthreads();

    const float* xo = &g_xout[b * Gg + 16];
    for (int e = tid; e < Hh; e += 128) {
        int l = e / CHc, j = e - l * CHc;
        float fg = sigf(xo[l * CHc + j]);
        float ig = sigf(xo[(Ll + l) * CHc + j]);
        float og = sigf(xo[(2 * Ll + l) * CHc + j]);
        float ci = tanhf(xo[(3 * Ll + l) * CHc + j]);
        float cl = g_c[b * Hh + e];
        float fmv = fm[l], imv = im[l], ovv = fmv * imv;
        float cn = ovv * (fg * cl + ig * ci) + (fmv - ovv) * cl + (imv - ovv) * ci;
        float hn = og * tanhf(cn);
        g_c[b * Hh + e] = cn;
        g_h[b * Hh + e] = hn;
        g_tmp_h[(slot * Bsz + b) * Hh + e] = hn;
        if (mine) g_hsnap[b * Hh + e] = hn;
    }

    if (!g_needed[t]) return;
    __syncthreads();

    if (tid == 0) {
        float d[KW], c = 0.f;
        for (int k = 0; k < KW; k++) {
            int sk = (t + 1 + k) % KW;
            c += g_tmp_dis[sk * Bsz + b];
            d[k] = c;
        }
        float m = -1e30f;
        for (int k = 0; k < KW; k++) m = fmaxf(m, d[k]);
        float tot = 0.f;
        for (int k = 0; k < KW; k++) { d[k] = expf(d[k] - m); tot += d[k]; }
        float inv = 1.f / tot;
        for (int k = 0; k < KW; k++) ldl[k] = d[k] * inv;
    }
    __syncthreads();

    for (int e = tid; e < Hh; e += 128) {
        float s = 0.f;
        for (int k = 0; k < KW; k++) {
            int sk = (t + 1 + k) % KW;
            float lv = ldl[k] * g_tmp_h[(sk * Bsz + b) * Hh + e];
            s += lv;
            if (mine) g_localh[b * KCV + k * Hh + e] = lv;   // snapshot window for post conv
        }
        thm[e] = s * (1.f / KW);
    }
    __syncthreads();

    if (tid < 64) {
        float a = bs[tid];
        const float* w = &Ws[tid * Hh];
        for (int kk = 0; kk < Hh; kk++) a += thm[kk] * w[kk];
        s64[tid] = fmaxf(a, 0.f);
    }
    __syncthreads();

    if (mine) {
        for (int e = tid; e < Hh; e += 128) {
            float a = brs[e];
            const float* w = &Wrs[e * 64];
#pragma unroll
            for (int kk = 0; kk < 64; kk++) a += s64[kk] * w[kk];
            g_theme[b * Hh + e] = sigf(a);
        }
    }
}

// ---------------- post-loop conv GEMM: convout[b][o] = localh[b] . Wct[:, o] ----------------
// M=256 (b), N=384 (o), K=3840 (j*Hh+h). B = g_Wct is K-major already.
__global__ __launch_bounds__(256) void k_conv2()
{
    __shared__ float As[RBK][RBM];
    __shared__ float Bs[RBK][RBN];
    const int tid = threadIdx.x;
    const int tx = tid & 15, ty = tid >> 4;
    const int o0 = blockIdx.x * RBN;
    const int b0 = blockIdx.y * RBM;
    const int rA0 = tid >> 3, cA0 = tid & 7, rA1 = rA0 + 32;
    const int rB0 = tid >> 4, cB0 = tid & 15, rB1 = rB0 + 16;

    float acc[4][4] = {};
    float4 a_s0, a_s1, b_s0, b_s1;

#define C2_LOAD(kc_) {                                                            \
    int kb_ = (kc_) * RBK;                                                        \
    a_s0 = *(const float4*)(&g_localh[(b0 + rA0) * KCV + kb_ + (cA0 << 2)]);      \
    a_s1 = *(const float4*)(&g_localh[(b0 + rA1) * KCV + kb_ + (cA0 << 2)]);      \
    b_s0 = *(const float4*)(&g_Wct[(size_t)(kb_ + rB0) * Hh + o0 + (cB0 << 2)]);  \
    b_s1 = *(const float4*)(&g_Wct[(size_t)(kb_ + rB1) * Hh + o0 + (cB0 << 2)]);  \
    }
#define C2_STORE() {                                                              \
    As[(cA0 << 2) + 0][rA0] = a_s0.x; As[(cA0 << 2) + 1][rA0] = a_s0.y;           \
    As[(cA0 << 2) + 2][rA0] = a_s0.z; As[(cA0 << 2) + 3][rA0] = a_s0.w;           \
    As[(cA0 << 2) + 0][rA1] = a_s1.x; As[(cA0 << 2) + 1][rA1] = a_s1.y;           \
    As[(cA0 << 2) + 2][rA1] = a_s1.z; As[(cA0 << 2) + 3][rA1] = a_s1.w;           \
    *(float4*)(&Bs[rB0][cB0 << 2]) = b_s0;                                        \
    *(float4*)(&Bs[rB1][cB0 << 2]) = b_s1;                                        \
    }

    C2_LOAD(0);
    C2_STORE();
    __syncthreads();
    for (int kc = 1; kc < KCV / RBK; kc++) {
        C2_LOAD(kc);
        RC_COMPUTE();
        __syncthreads();
        C2_STORE();
        __syncthreads();
    }
    RC_COMPUTE();

#pragma unroll
    for (int i = 0; i < 4; i++) {
        int b = b0 + (ty << 2) + i;
#pragma unroll
        for (int jj = 0; jj < 4; jj++) {
            int o = o0 + (tx << 2) + jj;
            g_convout[b * Hh + o] = acc[i][jj];
        }
    }
}

// ---------------- final: r = hsnap + theme*(conv+bc); out = r @ Wo.T + bo ----------------
__global__ __launch_bounds__(128) void k_out2(const float* __restrict__ bc,
                                              const float* __restrict__ bo,
                                              float* __restrict__ out)
{
    int b = blockIdx.x, o = threadIdx.x;
    __shared__ float r[Hh];
    for (int e = o; e < Hh; e += 128)
        r[e] = g_hsnap[b * Hh + e] + g_theme[b * Hh + e] * (g_convout[b * Hh + e] + bc[e]);
    __syncthreads();
    float a = bo[o];
    for (int k = 0; k < Hh; k++) a += r[k] * g_Wot[k * OUTd + o];
    out[b * OUTd + o] = a;
}

// ---------------- launch: split chunks -> GEMM chunks -> scan chunks, all pipelined ----------------
#define NCHUNKS 3
static const int c_vlo[NCHUNKS] = {0, 22, 44};
static const int c_vhi[NCHUNKS] = {22, 44, 50};

extern "C" void kernel_launch(void* const* d_in, const int* in_sizes, int n_in,
                              void* d_out, int out_size)
{
    const int*           node_ids    = (const int*)d_in[0];
    const float*         visit_times = (const float*)d_in[3];
    const unsigned char* attn_mask   = (const unsigned char*)d_in[5];
    const float*         embed       = (const float*)d_in[6];
    const float*         Wk          = (const float*)d_in[7];
    const float*         bk          = (const float*)d_in[8];
    const float*         Wr          = (const float*)d_in[9];
    const float*         br          = (const float*)d_in[10];
    const float*         Ws          = (const float*)d_in[11];
    const float*         bs          = (const float*)d_in[12];
    const float*         Wrs         = (const float*)d_in[13];
    const float*         brs         = (const float*)d_in[14];
    const float*         Wc          = (const float*)d_in[15];
    const float*         bc          = (const float*)d_in[16];
    const float*         Wo          = (const float*)d_in[17];
    const float*         bo          = (const float*)d_in[18];
    float*               out         = (float*)d_out;

    static int inited = 0;
    static cudaStream_t s2, s3;
    static cudaEvent_t evFork, evJoin, evC[NCHUNKS], evS[NCHUNKS];
    if (!inited) {
        cudaFuncSetAttribute(k_xk_mma, cudaFuncAttributeMaxDynamicSharedMemorySize, NSTG * STGB);
        cudaStreamCreateWithFlags(&s2, cudaStreamNonBlocking);
        cudaStreamCreateWithFlags(&s3, cudaStreamNonBlocking);
        cudaEventCreateWithFlags(&evFork, cudaEventDisableTiming);
        cudaEventCreateWithFlags(&evJoin, cudaEventDisableTiming);
        for (int c = 0; c < NCHUNKS; c++) {
            cudaEventCreateWithFlags(&evC[c], cudaEventDisableTiming);
            cudaEventCreateWithFlags(&evS[c], cudaEventDisableTiming);
        }
        inited = 1;
    }

    // ---- prep on primary stream ----
    k_zero<<<512, 256>>>();
    k_last<<<Bsz, 64>>>(attn_mask);
    k_wtrans<<<512, 256>>>(Wc, Wo);
    k_wkbf<<<2048, 256>>>(Wk);

    // fork s2 (scan) and s3 (A split) from primary
    cudaEventRecord(evFork, 0);
    cudaStreamWaitEvent(s2, evFork, 0);
    cudaStreamWaitEvent(s3, evFork, 0);

    // ---- A-split chunks on s3; GEMM chunk c waits on split chunk c ----
    for (int c = 0; c < NCHUNKS; c++) {
        int t0 = c_vlo[c] * 2 * 256;
        int nt = (c_vhi[c] - c_vlo[c]) * 2 * 256;
        k_split_rng<<<4096, 256, 0, s3>>>(node_ids, (const float4*)embed, t0, nt);
        cudaEventRecord(evS[c], s3);
    }

    // ---- GEMM chunks on primary; gated on their split chunk ----
    for (int c = 0; c < NCHUNKS; c++) {
        cudaStreamWaitEvent(0, evS[c], 0);
        int mi0 = c_vlo[c] * 2;
        int nmt = (c_vhi[c] - c_vlo[c]) * 2;
        dim3 gx(13, nmt);
        k_xk_mma<<<gx, 256, NSTG * STGB, 0>>>(visit_times, Wk, bk, Wr, br, mi0);
        cudaEventRecord(evC[c], 0);
    }

    // ---- scan chunks on s2 (rec+cell only), each gated on its GEMM chunk ----
    for (int c = 0; c < NCHUNKS; c++) {
        cudaStreamWaitEvent(s2, evC[c], 0);
        for (int t = c_vlo[c]; t < c_vhi[c]; t++) {
            dim3 gr(25, 4);
            k_rec<<<gr, 256, 0, s2>>>(Wr, t);
            k_cell<<<Bsz, 128, 0, s2>>>(Ws, bs, Wrs, brs, t);
        }
    }
    // post-loop: single conv GEMM over snapshots + fused output
    {
        dim3 gc(6, 4);
        k_conv2<<<gc, 256, 0, s2>>>();
        k_out2<<<Bsz, 128, 0, s2>>>(bc, bo, out);
    }

    // join back to primary stream
    cudaEventRecord(evJoin, s2);
    cudaStreamWaitEvent(0, evJoin, 0);
}

// round 16
// speedup vs baseline: 1.4577x; 1.0004x over previous
#include <cuda_runtime.h>
#include <cuda_fp16.h>
#include <math.h>
#include <stdint.h>

#define Bsz 256
#define Vn  50
#define Nn  64
#define Dd  128
#define NDd 8192
#define Hh  384
#define Ll  8
#define CHc 48
#define KW  10
#define OUTd 128
#define Gg  1552
#define GgPad 1664
#define Mtot 12800          /* B*V ; m = v*Bsz + b (v-major) */
#define NIT 256             /* 8192 / 32 */
#define NSTG 4              /* pipeline stages, 16KB each */
#define STGB 16384
#define KCV (KW * Hh)       /* 3840: conv contraction dim */

typedef unsigned long long ull;

// ---------------- device scratch (no allocs allowed) ----------------
__device__ float g_xk[(size_t)Mtot * Gg];          // [v*Bsz+b][g]
__device__ float g_xout[Bsz * Gg];
__device__ float g_h[Bsz * Hh];
__device__ float g_c[Bsz * Hh];
__device__ float g_tmp_h[KW * Bsz * Hh];
__device__ float g_tmp_dis[KW * Bsz];
__device__ float g_theme[Bsz * Hh];
__device__ float g_localh[Bsz * KCV];              // snapshot: ld[k]*tmp_h at b's last step
__device__ float g_hsnap[Bsz * Hh];                // snapshot: h at b's last step
__device__ float g_convout[Bsz * Hh];
__device__ float g_Wct[KW * Hh * Hh];              // [(j*Hh+h)][o]  (K-major for conv GEMM)
__device__ float g_Wot[Hh * OUTd];
__device__ int   g_last[Bsz];
__device__ int   g_needed[64];
// pre-tiled, pre-swizzled 8KB tiles: [tileIdx*256 + ck] * 4096 fp16 elems
__device__ __align__(256) __half g_Wk_h[(size_t)GgPad * NDd];
__device__ __align__(256) __half g_A_h[(size_t)Mtot * NDd];

__device__ __forceinline__ float sigf(float x) { return 1.0f / (1.0f + expf(-x)); }

__device__ __forceinline__ uint32_t smem_u32(const void* p) {
    uint32_t a;
    asm("{ .reg .u64 t; cvta.to.shared.u64 t, %1; cvt.u32.u64 %0, t; }" : "=r"(a) : "l"(p));
    return a;
}

// ---------------- sm_90-era async + sm_80 tensor path (valid under .target sm_103) ----------------
__device__ __forceinline__ void ldm4(uint32_t* r, uint32_t addr) {
    asm volatile("ldmatrix.sync.aligned.m8n8.x4.shared.b16 {%0,%1,%2,%3}, [%4];"
                 : "=r"(r[0]), "=r"(r[1]), "=r"(r[2]), "=r"(r[3]) : "r"(addr));
}
__device__ __forceinline__ void mma16816h(float* c, const uint32_t* a, const uint32_t* b) {
    asm volatile("mma.sync.aligned.m16n8k16.row.col.f32.f16.f16.f32 "
                 "{%0,%1,%2,%3}, {%4,%5,%6,%7}, {%8,%9}, {%0,%1,%2,%3};"
                 : "+f"(c[0]), "+f"(c[1]), "+f"(c[2]), "+f"(c[3])
                 : "r"(a[0]), "r"(a[1]), "r"(a[2]), "r"(a[3]), "r"(b[0]), "r"(b[1]));
}

#define MB_INIT(a, c) \
    asm volatile("mbarrier.init.shared.b64 [%0], %1;" :: "r"((uint32_t)(a)), "r"((uint32_t)(c)) : "memory")
#define MB_EXPECT(a, tx) \
    asm volatile("mbarrier.arrive.expect_tx.shared.b64 _, [%0], %1;" :: "r"((uint32_t)(a)), "r"((uint32_t)(tx)) : "memory")
#define MB_WAIT(a, par) do {                                                       \
    uint32_t _m = (uint32_t)(a), _p = (uint32_t)(par), _d;                         \
    asm volatile("{\n\t.reg .pred p;\n\t"                                          \
        "mbarrier.try_wait.parity.shared.b64 p, [%1], %2;\n\t"                     \
        "selp.b32 %0, 1, 0, p;\n\t}" : "=r"(_d) : "r"(_m), "r"(_p) : "memory");    \
    if (!_d) {                                                                     \
        asm volatile("{\n\t.reg .pred P1;\n\t"                                     \
        "WL_%=:\n\t"                                                               \
        "mbarrier.try_wait.parity.shared.b64 P1, [%0], %1;\n\t"                    \
        "@P1 bra.uni WD_%=;\n\t"                                                   \
        "bra.uni WL_%=;\n\t"                                                       \
        "WD_%=:\n\t}" :: "r"(_m), "r"(_p) : "memory");                             \
    } } while (0)
#define FENCE_ASYNC() asm volatile("fence.proxy.async.shared::cta;" ::: "memory")
#define BULK_G2S(dst, src, sz, mbar) \
    asm volatile("cp.async.bulk.shared::cta.global.mbarrier::complete_tx::bytes [%0], [%1], %2, [%3];" \
        :: "r"((uint32_t)(dst)), "l"(__cvta_generic_to_global(src)), "r"((uint32_t)(sz)), "r"((uint32_t)(mbar)) : "memory")

// ---------------- small init kernels ----------------
__global__ void k_zero() {
    int i = blockIdx.x * blockDim.x + threadIdx.x;
    int st = gridDim.x * blockDim.x;
    for (int k = i; k < KW * Bsz * Hh; k += st) g_tmp_h[k] = 0.f;
    for (int k = i; k < Bsz * Hh; k += st) { g_c[k] = 0.f; g_h[k] = 0.f; }
    for (int k = i; k < KW * Bsz; k += st) g_tmp_dis[k] = 0.f;
    if (i < 64) g_needed[i] = 0;
}

__global__ void k_last(const unsigned char* __restrict__ mask) {
    int b = blockIdx.x, v = threadIdx.x;   // blockDim = 64
    __shared__ int nv[64];
    int val = 0;
    if (v < Vn) {
        const unsigned char* mp = mask + ((size_t)b * Vn + v) * Nn;
        int allp = 1;
        for (int n = 0; n < Nn; n++) allp &= (mp[n] != 0);
        val = allp ? 0 : 1;
    }
    nv[v] = val;
    __syncthreads();
    if (v == 0) {
        int c = 0;
        for (int i = 0; i < Vn; i++) c += nv[i];
        int last = c - 1;
        if (last < 0) last += Vn;
        g_last[b] = last;
        g_needed[last] = 1;
    }
}

__global__ void k_wtrans(const float* __restrict__ Wc, const float* __restrict__ Wo) {
    int i = blockIdx.x * blockDim.x + threadIdx.x;
    int st = gridDim.x * blockDim.x;
    for (int idx = i; idx < Hh * Hh * KW; idx += st) {
        int o = idx / (Hh * KW);
        int rem = idx - o * (Hh * KW);
        int h = rem / KW;
        int j = rem - h * KW;
        g_Wct[((size_t)j * Hh + h) * Hh + o] = Wc[idx];
    }
    for (int idx = i; idx < OUTd * Hh; idx += st) {
        int o = idx / Hh, k = idx - o * Hh;
        g_Wot[k * OUTd + o] = Wo[idx];
    }
}

// decode physical element-group position -> (tileRow, logical k-chunk elem)
__device__ __forceinline__ void dec_tile(size_t e4, int& tile, int& row, int& kk) {
    tile = (int)(e4 >> 10);                    // 1024 groups per 8KB tile
    int off = ((int)e4 & 1023) * 8;            // byte offset in tile
    row = off >> 6;
    int w = off & 63;
    int chp = w >> 4;
    int ch = chp ^ ((row >> 1) & 3);
    kk = ch * 8 + ((w & 15) >> 1);             // 0..28, step 4
}

__device__ __forceinline__ uint32_t pkh(__half a, __half b) {
    __half2 t; t.x = a; t.y = b;
    return *(uint32_t*)&t;
}

// convert Wk[:, :8192] to fp16 tiles [ni*256+ck] (GgPad rows, zero pad)
__global__ void k_wkbf(const float* __restrict__ Wk) {
    size_t i = (size_t)blockIdx.x * blockDim.x + threadIdx.x;
    size_t st = (size_t)gridDim.x * blockDim.x;
    const size_t TOT4 = (size_t)GgPad * NDd / 4;
    uint2* ph = (uint2*)g_Wk_h;
    for (size_t e4 = i; e4 < TOT4; e4 += st) {
        int tile, row, kk;
        dec_tile(e4, tile, row, kk);
        int ni = tile >> 8, ck = tile & 255;
        int g = ni * 128 + row;
        int k = ck * 32 + kk;
        float v0 = 0.f, v1 = 0.f, v2 = 0.f, v3 = 0.f;
        if (g < Gg) {
            const float* wr = Wk + (size_t)g * (NDd + 1) + k;
            v0 = wr[0]; v1 = wr[1]; v2 = wr[2]; v3 = wr[3];
        }
        ph[e4] = make_uint2(pkh(__float2half_rn(v0), __float2half_rn(v1)),
                            pkh(__float2half_rn(v2), __float2half_rn(v3)));
    }
}

// gather x = embed[node_ids] -> fp16 tiles [mi*256+ck]; m = v*Bsz+b
__global__ void k_split_rng(const int* __restrict__ ids, const float4* __restrict__ ef4,
                            int tile0, int ntiles) {
    size_t i = (size_t)blockIdx.x * blockDim.x + threadIdx.x;
    size_t st = (size_t)gridDim.x * blockDim.x;
    const size_t base = (size_t)tile0 << 10;
    const size_t CNT4 = (size_t)ntiles << 10;
    uint2* ph = (uint2*)g_A_h;
    for (size_t r = i; r < CNT4; r += st) {
        size_t e4 = base + r;
        int tile, row, kk;
        dec_tile(e4, tile, row, kk);
        int mi = tile >> 8, ck = tile & 255;
        int m = mi * 128 + row;
        int k = ck * 32 + kk;
        int v_ = m >> 8, b = m & 255;
        int id = __ldg(&ids[(b * Vn + v_) * Nn + (k >> 7)]);
        float4 v = __ldg(&ef4[(size_t)id * 32 + ((k & 127) >> 2)]);
        ph[e4] = make_uint2(pkh(__float2half_rn(v.x), __float2half_rn(v.y)),
                            pkh(__float2half_rn(v.z), __float2half_rn(v.w)));
    }
}

// ---------------- tensor-core input projection: bulk-TMA loader + fp16 mma.sync ----------------
__global__ __launch_bounds__(256, 2)
void k_xk_mma(const float* __restrict__ vt, const float* __restrict__ Wk,
              const float* __restrict__ bk, const float* __restrict__ Wr,
              const float* __restrict__ br, int mi0)
{
    extern __shared__ char dsm[];
    __shared__ float bias_s[128], wl_s[128], vt_s[128];
    __shared__ __align__(8) ull mbars[NSTG];
    const uint32_t smb = smem_u32(dsm);
    const int tid = threadIdx.x;
    const int wid = tid >> 5, lane = tid & 31;
    const int wm = wid & 1, wn = wid >> 1;    // warp tile: 64 rows x 32 cols

    const int mi = mi0 + blockIdx.y;
    const int ni = blockIdx.x;
    const int m0 = mi * 128, n0 = ni * 128;

    if (tid < NSTG) MB_INIT(smem_u32(&mbars[tid]), 1);
    if (tid < 128) {
        int g = n0 + tid;
        if (g < Gg) {
            bias_s[tid] = bk[g] + br[g];
            wl_s[tid] = Wk[(size_t)g * (NDd + 1) + NDd] + Wr[(size_t)g * (Hh + 1) + Hh];
        } else { bias_s[tid] = 0.f; wl_s[tid] = 0.f; }
        int m = m0 + tid;
        int v_ = m >> 8, b = m & 255;
        vt_s[tid] = __ldg(&vt[b * Vn + v_]);
    }
    FENCE_ASYNC();
    __syncthreads();

    float acc[4][4][4];
#pragma unroll
    for (int a = 0; a < 4; a++)
#pragma unroll
        for (int b = 0; b < 4; b++)
#pragma unroll
            for (int c = 0; c < 4; c++) acc[a][b][c] = 0.f;

    if (tid == 0) {
#pragma unroll
        for (int s = 0; s < NSTG - 1; s++) {
            uint32_t mb = smem_u32(&mbars[s]);
            uint32_t so = smb + s * STGB;
            size_t at = ((size_t)mi * 256 + s) * 4096;
            size_t bt = ((size_t)ni * 256 + s) * 4096;
            MB_EXPECT(mb, (uint32_t)STGB);
            BULK_G2S(so,        g_A_h  + at, 8192u, mb);
            BULK_G2S(so + 8192, g_Wk_h + bt, 8192u, mb);
        }
    }

    for (int ck = 0; ck < NIT; ck++) {
        const int st = ck & (NSTG - 1);
        MB_WAIT(smem_u32(&mbars[st]), (ck >> 2) & 1);

        uint32_t so = smb + st * STGB;
#pragma unroll
        for (int kc = 0; kc < 2; kc++) {
            uint32_t a_f[4][4], b_f[4][2];
            const int arow = wm * 64 + (lane & 15);
            const int ach = 2 * kc + (lane >> 4);
#pragma unroll
            for (int mt = 0; mt < 4; mt++) {
                int r = arow + mt * 16;
                uint32_t ph = (uint32_t)(r * 64 + ((ach ^ ((r >> 1) & 3)) << 4));
                ldm4(a_f[mt], so + ph);
            }
            const int brow = wn * 32 + ((lane >> 4) & 1) * 8 + (lane & 7);
            const int bch = 2 * kc + ((lane >> 3) & 1);
#pragma unroll
            for (int np = 0; np < 2; np++) {
                int r = brow + np * 16;
                uint32_t ph = (uint32_t)(r * 64 + ((bch ^ ((r >> 1) & 3)) << 4));
                uint32_t t[4];
                ldm4(t, so + 8192 + ph);
                b_f[np * 2][0] = t[0]; b_f[np * 2][1] = t[1];
                b_f[np * 2 + 1][0] = t[2]; b_f[np * 2 + 1][1] = t[3];
            }
#pragma unroll
            for (int mt = 0; mt < 4; mt++)
#pragma unroll
                for (int nt = 0; nt < 4; nt++) mma16816h(acc[mt][nt], a_f[mt], b_f[nt]);
        }
        __syncthreads();
        if (tid == 0 && ck + NSTG - 1 < NIT) {
            int nk = ck + NSTG - 1;
            int ns = nk & (NSTG - 1);
            uint32_t mb = smem_u32(&mbars[ns]);
            uint32_t nso = smb + ns * STGB;
            size_t at = ((size_t)mi * 256 + nk) * 4096;
            size_t bt = ((size_t)ni * 256 + nk) * 4096;
            MB_EXPECT(mb, (uint32_t)STGB);
            BULK_G2S(nso,        g_A_h  + at, 8192u, mb);
            BULK_G2S(nso + 8192, g_Wk_h + bt, 8192u, mb);
        }
    }

#pragma unroll
    for (int mt = 0; mt < 4; mt++) {
        int rl0 = wm * 64 + mt * 16 + (lane >> 2);
        int rl1 = rl0 + 8;
        float v0 = vt_s[rl0], v1 = vt_s[rl1];
        size_t ro0 = (size_t)(m0 + rl0) * Gg;
        size_t ro1 = (size_t)(m0 + rl1) * Gg;
#pragma unroll
        for (int nt = 0; nt < 4; nt++) {
            int gl = wn * 32 + nt * 8 + (lane & 3) * 2;
            int g = n0 + gl;
            if (g < Gg) {
                g_xk[ro0 + g] = acc[mt][nt][0] + bias_s[gl] + v0 * wl_s[gl];
                g_xk[ro1 + g] = acc[mt][nt][2] + bias_s[gl] + v1 * wl_s[gl];
            }
            if (g + 1 < Gg) {
                g_xk[ro0 + g + 1] = acc[mt][nt][1] + bias_s[gl + 1] + v0 * wl_s[gl + 1];
                g_xk[ro1 + g + 1] = acc[mt][nt][3] + bias_s[gl + 1] + v1 * wl_s[gl + 1];
            }
        }
    }
}

// ---------------- recurrent GEMM: xout = XK[t*Bsz+b] + h @ Wr[:, :H].T ----------------
#define RBM 64
#define RBN 64
#define RBK 32

#define RC_LOAD(kc_) {                                                          \
    int kb_ = (kc_) * RBK;                                                      \
    a_s0 = *(const float4*)(&g_h[(b0 + rA0) * Hh + kb_ + (cA0 << 2)]);          \
    a_s1 = *(const float4*)(&g_h[(b0 + rA1) * Hh + kb_ + (cA0 << 2)]);          \
    _Pragma("unroll")                                                           \
    for (int i_ = 0; i_ < 8; i_++) {                                            \
        int e_ = (i_ << 8) + tid; int kl_ = e_ & 31, gl_ = e_ >> 5;             \
        int g_ = g0 + gl_;                                                      \
        b_s[i_] = (g_ < Gg) ? Wr[(size_t)g_ * (Hh + 1) + kb_ + kl_] : 0.f;      \
    } }

#define RC_STORE() {                                                            \
    As[(cA0 << 2) + 0][rA0] = a_s0.x; As[(cA0 << 2) + 1][rA0] = a_s0.y;         \
    As[(cA0 << 2) + 2][rA0] = a_s0.z; As[(cA0 << 2) + 3][rA0] = a_s0.w;         \
    As[(cA0 << 2) + 0][rA1] = a_s1.x; As[(cA0 << 2) + 1][rA1] = a_s1.y;         \
    As[(cA0 << 2) + 2][rA1] = a_s1.z; As[(cA0 << 2) + 3][rA1] = a_s1.w;         \
    _Pragma("unroll")                                                           \
    for (int i_ = 0; i_ < 8; i_++) {                                            \
        int e_ = (i_ << 8) + tid; Bs[e_ & 31][e_ >> 5] = b_s[i_];               \
    } }

#define RC_COMPUTE() {                                                          \
    _Pragma("unroll")                                                           \
    for (int kk = 0; kk < RBK; kk++) {                                          \
        float4 av_ = *(const float4*)(&As[kk][ty << 2]);                        \
        float4 bv_ = *(const float4*)(&Bs[kk][tx << 2]);                        \
        float aa_[4] = {av_.x, av_.y, av_.z, av_.w};                            \
        float bb_[4] = {bv_.x, bv_.y, bv_.z, bv_.w};                            \
        _Pragma("unroll")                                                       \
        for (int i_ = 0; i_ < 4; i_++)                                          \
            _Pragma("unroll")                                                   \
            for (int j_ = 0; j_ < 4; j_++)                                      \
                acc[i_][j_] += aa_[i_] * bb_[j_];                               \
    } }

__global__ __launch_bounds__(256) void k_rec(const float* __restrict__ Wr, int t)
{
    __shared__ float As[RBK][RBM];
    __shared__ float Bs[RBK][RBN];
    const int tid = threadIdx.x;
    const int tx = tid & 15, ty = tid >> 4;
    const int g0 = blockIdx.x * RBN;
    const int b0 = blockIdx.y * RBM;
    const int rA0 = tid >> 3, cA0 = tid & 7, rA1 = rA0 + 32;

    float acc[4][4] = {};
    float4 a_s0, a_s1;
    float b_s[8];

    RC_LOAD(0);
    RC_STORE();
    __syncthreads();
    for (int kc = 1; kc < Hh / RBK; kc++) {
        RC_LOAD(kc);
        RC_COMPUTE();
        __syncthreads();
        RC_STORE();
        __syncthreads();
    }
    RC_COMPUTE();

#pragma unroll
    for (int i = 0; i < 4; i++) {
        int b = b0 + (ty << 2) + i;
#pragma unroll
        for (int j = 0; j < 4; j++) {
            int g = g0 + (tx << 2) + j;
            if (g < Gg)
                g_xout[b * Gg + g] = acc[i][j] + g_xk[((size_t)t * Bsz + b) * Gg + g];
        }
    }
}

// ---------------- LSTM cell + ring + local_dis + theme + snapshots ----------------
__global__ __launch_bounds__(128) void k_cell(
    const float* __restrict__ Ws, const float* __restrict__ bs,
    const float* __restrict__ Wrs, const float* __restrict__ brs, int t)
{
    const int b = blockIdx.x, tid = threadIdx.x;
    __shared__ float z16[16];
    __shared__ float fm[Ll], im[Ll];
    __shared__ float thm[Hh];
    __shared__ float s64[64];
    __shared__ float ldl[KW];

    if (tid < 16) z16[tid] = g_xout[b * Gg + tid];
    __syncthreads();

    const int slot = t % KW;
    const int mine = (g_last[b] == t);
    if (tid == 0) {
        float m = -1e30f;
        for (int i = 0; i < Ll; i++) m = fmaxf(m, z16[i]);
        float s[Ll], tot = 0.f;
        for (int i = 0; i < Ll; i++) { s[i] = expf(z16[i] - m); tot += s[i]; }
        float inv = 1.f / tot, cum = 0.f, msum = 0.f;
        for (int i = 0; i < Ll; i++) { cum += s[i] * inv; fm[i] = cum; msum += cum; }
        g_tmp_dis[slot * Bsz + b] = 1.f - msum * (1.f / Ll);
    }
    if (tid == 1) {
        float m = -1e30f;
        for (int i = 0; i < Ll; i++) m = fmaxf(m, z16[8 + i]);
        float s[Ll], tot = 0.f;
        for (int i = 0; i < Ll; i++) { s[i] = expf(z16[8 + i] - m); tot += s[i]; }
        float inv = 1.f / tot, cum = 0.f;
        for (int i = Ll - 1; i >= 0; i--) { cum += s[i] * inv; im[i] = cum; }
    }
    __syncthreads();

    const float* xo = &g_xout[b * Gg + 16];
    for (int e = tid; e < Hh; e += 128) {
        int l = e / CHc, j = e - l * CHc;
        float fg = sigf(xo[l * CHc + j]);
        float ig = sigf(xo[(Ll + l) * CHc + j]);
        float og = sigf(xo[(2 * Ll + l) * CHc + j]);
        float ci = tanhf(xo[(3 * Ll + l) * CHc + j]);
        float cl = g_c[b * Hh + e];
        float fmv = fm[l], imv = im[l], ovv = fmv * imv;
        float cn = ovv * (fg * cl + ig * ci) + (fmv - ovv) * cl + (imv - ovv) * ci;
        float hn = og * tanhf(cn);
        g_c[b * Hh + e] = cn;
        g_h[b * Hh + e] = hn;
        g_tmp_h[(slot * Bsz + b) * Hh + e] = hn;
        if (mine) g_hsnap[b * Hh + e] = hn;
    }

    if (!g_needed[t]) return;
    __syncthreads();

    if (tid == 0) {
        float d[KW], c = 0.f;
        for (int k = 0; k < KW; k++) {
            int sk = (t + 1 + k) % KW;
            c += g_tmp_dis[sk * Bsz + b];
            d[k] = c;
        }
        float m = -1e30f;
        for (int k = 0; k < KW; k++) m = fmaxf(m, d[k]);
        float tot = 0.f;
        for (int k = 0; k < KW; k++) { d[k] = expf(d[k] - m); tot += d[k]; }
        float inv = 1.f / tot;
        for (int k = 0; k < KW; k++) ldl[k] = d[k] * inv;
    }
    __syncthreads();

    for (int e = tid; e < Hh; e += 128) {
        float s = 0.f;
        for (int k = 0; k < KW; k++) {
            int sk = (t + 1 + k) % KW;
            float lv = ldl[k] * g_tmp_h[(sk * Bsz + b) * Hh + e];
            s += lv;
            if (mine) g_localh[b * KCV + k * Hh + e] = lv;   // snapshot window for post conv
        }
        thm[e] = s * (1.f / KW);
    }
    __syncthreads();

    if (tid < 64) {
        float a = bs[tid];
        const float* w = &Ws[tid * Hh];
        for (int kk = 0; kk < Hh; kk++) a += thm[kk] * w[kk];
        s64[tid] = fmaxf(a, 0.f);
    }
    __syncthreads();

    if (mine) {
        for (int e = tid; e < Hh; e += 128) {
            float a = brs[e];
            const float* w = &Wrs[e * 64];
#pragma unroll
            for (int kk = 0; kk < 64; kk++) a += s64[kk] * w[kk];
            g_theme[b * Hh + e] = sigf(a);
        }
    }
}

// ---------------- post-loop conv GEMM: convout[b][o] = localh[b] . Wct[:, o] ----------------
// M=256 (b), N=384 (o), K=3840 (j*Hh+h). B = g_Wct is K-major already.
__global__ __launch_bounds__(256) void k_conv2()
{
    __shared__ float As[RBK][RBM];
    __shared__ float Bs[RBK][RBN];
    const int tid = threadIdx.x;
    const int tx = tid & 15, ty = tid >> 4;
    const int o0 = blockIdx.x * RBN;
    const int b0 = blockIdx.y * RBM;
    const int rA0 = tid >> 3, cA0 = tid & 7, rA1 = rA0 + 32;
    const int rB0 = tid >> 4, cB0 = tid & 15, rB1 = rB0 + 16;

    float acc[4][4] = {};
    float4 a_s0, a_s1, b_s0, b_s1;

#define C2_LOAD(kc_) {                                                            \
    int kb_ = (kc_) * RBK;                                                        \
    a_s0 = *(const float4*)(&g_localh[(b0 + rA0) * KCV + kb_ + (cA0 << 2)]);      \
    a_s1 = *(const float4*)(&g_localh[(b0 + rA1) * KCV + kb_ + (cA0 << 2)]);      \
    b_s0 = *(const float4*)(&g_Wct[(size_t)(kb_ + rB0) * Hh + o0 + (cB0 << 2)]);  \
    b_s1 = *(const float4*)(&g_Wct[(size_t)(kb_ + rB1) * Hh + o0 + (cB0 << 2)]);  \
    }
#define C2_STORE() {                                                              \
    As[(cA0 << 2) + 0][rA0] = a_s0.x; As[(cA0 << 2) + 1][rA0] = a_s0.y;           \
    As[(cA0 << 2) + 2][rA0] = a_s0.z; As[(cA0 << 2) + 3][rA0] = a_s0.w;           \
    As[(cA0 << 2) + 0][rA1] = a_s1.x; As[(cA0 << 2) + 1][rA1] = a_s1.y;           \
    As[(cA0 << 2) + 2][rA1] = a_s1.z; As[(cA0 << 2) + 3][rA1] = a_s1.w;           \
    *(float4*)(&Bs[rB0][cB0 << 2]) = b_s0;                                        \
    *(float4*)(&Bs[rB1][cB0 << 2]) = b_s1;                                        \
    }

    C2_LOAD(0);
    C2_STORE();
    __syncthreads();
    for (int kc = 1; kc < KCV / RBK; kc++) {
        C2_LOAD(kc);
        RC_COMPUTE();
        __syncthreads();
        C2_STORE();
        __syncthreads();
    }
    RC_COMPUTE();

#pragma unroll
    for (int i = 0; i < 4; i++) {
        int b = b0 + (ty << 2) + i;
#pragma unroll
        for (int jj = 0; jj < 4; jj++) {
            int o = o0 + (tx << 2) + jj;
            g_convout[b * Hh + o] = acc[i][jj];
        }
    }
}

// ---------------- final: r = hsnap + theme*(conv+bc); out = r @ Wo.T + bo ----------------
__global__ __launch_bounds__(128) void k_out2(const float* __restrict__ bc,
                                              const float* __restrict__ bo,
                                              float* __restrict__ out)
{
    int b = blockIdx.x, o = threadIdx.x;
    __shared__ float r[Hh];
    for (int e = o; e < Hh; e += 128)
        r[e] = g_hsnap[b * Hh + e] + g_theme[b * Hh + e] * (g_convout[b * Hh + e] + bc[e]);
    __syncthreads();
    float a = bo[o];
    for (int k = 0; k < Hh; k++) a += r[k] * g_Wot[k * OUTd + o];
    out[b * OUTd + o] = a;
}

// ---------------- launch: split chunks -> GEMM chunks -> scan chunks, all pipelined ----------------
#define NCHUNKS 3
static const int c_vlo[NCHUNKS] = {0, 22, 44};
static const int c_vhi[NCHUNKS] = {22, 44, 50};

extern "C" void kernel_launch(void* const* d_in, const int* in_sizes, int n_in,
                              void* d_out, int out_size)
{
    const int*           node_ids    = (const int*)d_in[0];
    const float*         visit_times = (const float*)d_in[3];
    const unsigned char* attn_mask   = (const unsigned char*)d_in[5];
    const float*         embed       = (const float*)d_in[6];
    const float*         Wk          = (const float*)d_in[7];
    const float*         bk          = (const float*)d_in[8];
    const float*         Wr          = (const float*)d_in[9];
    const float*         br          = (const float*)d_in[10];
    const float*         Ws          = (const float*)d_in[11];
    const float*         bs          = (const float*)d_in[12];
    const float*         Wrs         = (const float*)d_in[13];
    const float*         brs         = (const float*)d_in[14];
    const float*         Wc          = (const float*)d_in[15];
    const float*         bc          = (const float*)d_in[16];
    const float*         Wo          = (const float*)d_in[17];
    const float*         bo          = (const float*)d_in[18];
    float*               out         = (float*)d_out;

    static int inited = 0;
    static cudaStream_t s2, s3;
    static cudaEvent_t evFork, evJoin, evC[NCHUNKS], evS[NCHUNKS];
    if (!inited) {
        cudaFuncSetAttribute(k_xk_mma, cudaFuncAttributeMaxDynamicSharedMemorySize, NSTG * STGB);
        cudaStreamCreateWithFlags(&s2, cudaStreamNonBlocking);
        cudaStreamCreateWithFlags(&s3, cudaStreamNonBlocking);
        cudaEventCreateWithFlags(&evFork, cudaEventDisableTiming);
        cudaEventCreateWithFlags(&evJoin, cudaEventDisableTiming);
        for (int c = 0; c < NCHUNKS; c++) {
            cudaEventCreateWithFlags(&evC[c], cudaEventDisableTiming);
            cudaEventCreateWithFlags(&evS[c], cudaEventDisableTiming);
        }
        inited = 1;
    }

    // ---- prep on primary stream ----
    k_zero<<<512, 256>>>();
    k_last<<<Bsz, 64>>>(attn_mask);
    k_wtrans<<<512, 256>>>(Wc, Wo);
    k_wkbf<<<2048, 256>>>(Wk);

    // fork s2 (scan) and s3 (A split) from primary
    cudaEventRecord(evFork, 0);
    cudaStreamWaitEvent(s2, evFork, 0);
    cudaStreamWaitEvent(s3, evFork, 0);

    // ---- A-split chunks on s3; GEMM chunk c waits on split chunk c ----
    for (int c = 0; c < NCHUNKS; c++) {
        int t0 = c_vlo[c] * 2 * 256;
        int nt = (c_vhi[c] - c_vlo[c]) * 2 * 256;
        k_split_rng<<<4096, 256, 0, s3>>>(node_ids, (const float4*)embed, t0, nt);
        cudaEventRecord(evS[c], s3);
    }

    // ---- GEMM chunks on primary; gated on their split chunk ----
    for (int c = 0; c < NCHUNKS; c++) {
        cudaStreamWaitEvent(0, evS[c], 0);
        int mi0 = c_vlo[c] * 2;
        int nmt = (c_vhi[c] - c_vlo[c]) * 2;
        dim3 gx(13, nmt);
        k_xk_mma<<<gx, 256, NSTG * STGB, 0>>>(visit_times, Wk, bk, Wr, br, mi0);
        cudaEventRecord(evC[c], 0);
    }

    // ---- scan chunks on s2 (rec+cell only), each gated on its GEMM chunk ----
    for (int c = 0; c < NCHUNKS; c++) {
        cudaStreamWaitEvent(s2, evC[c], 0);
        for (int t = c_vlo[c]; t < c_vhi[c]; t++) {
            dim3 gr(25, 4);
            k_rec<<<gr, 256, 0, s2>>>(Wr, t);
            k_cell<<<Bsz, 128, 0, s2>>>(Ws, bs, Wrs, brs, t);
        }
    }
    // post-loop: single conv GEMM over snapshots + fused output
    {
        dim3 gc(6, 4);
        k_conv2<<<gc, 256, 0, s2>>>();
        k_out2<<<Bsz, 128, 0, s2>>>(bc, bo, out);
    }

    // join back to primary stream
    cudaEventRecord(evJoin, s2);
    cudaStreamWaitEvent(0, evJoin, 0);
}